// round 3
// baseline (speedup 1.0000x reference)
#include <cuda_runtime.h>
#include <cstdint>

#define T 4
#define BSZ 16
#define C 384
#define HW 256
#define NEXP 8
#define NCOL 1024   // T*HW columns, n = hw*4 + t
#define BM 128
#define BN 128
#define BK 32
#define NTHREADS 256

// ---------------- device scratch (no allocations allowed) ----------------
__device__ float g_S[BSZ * C];          // router spike-count sums
__device__ int   g_pair_e[BSZ * 2];     // expert index per (b, slot)
__device__ float g_pair_w[BSZ * 2];     // routing weight per (b, slot)
__device__ float g_H1[(size_t)32 * C * HW * T];  // h1 scratch [p][c][hw][t]

// ---------------- helpers ----------------
__device__ __forceinline__ uint32_t f2tf32(float f) {
    uint32_t r;
    asm("cvt.rna.tf32.f32 %0, %1;" : "=r"(r) : "f"(f));
    return r;
}

// ---------------- kernel: zero output ----------------
__global__ void zero_kernel(float4* out) {
    size_t i = (size_t)blockIdx.x * blockDim.x + threadIdx.x;
    out[i] = make_float4(0.f, 0.f, 0.f, 0.f);
}

// ---------------- kernel: router S[b,c] = sum_{t,hw} spike(lif(x, tau=2)) ----------------
__global__ void router_s_kernel(const float* __restrict__ x) {
    int bc = blockIdx.x;               // 0..BSZ*C-1
    int b = bc / C, c = bc % C;
    int hw = threadIdx.x;              // 256 threads = one hw each
    const float* px = x + (((size_t)b) * C + c) * HW + hw;
    float v = 0.f, cnt = 0.f;
#pragma unroll
    for (int t = 0; t < T; t++) {
        float xv = px[(size_t)t * BSZ * C * HW];
        v = v + (xv - v) / 2.0f;       // charge
        float s = (v >= 1.0f) ? 1.f : 0.f;
        cnt += s;
        v = v * (1.f - s);             // hard reset
    }
    __shared__ float red[256];
    red[hw] = cnt;
    __syncthreads();
    for (int o = 128; o > 0; o >>= 1) {
        if (hw < o) red[hw] += red[hw + o];
        __syncthreads();
    }
    if (hw == 0) g_S[bc] = red[0];
}

// ---------------- kernel: logits -> softmax -> top2 -> pair list ----------------
__global__ void routing_kernel(const float* __restrict__ rW, const float* __restrict__ rb,
                               const float* __restrict__ rbs, const float* __restrict__ rbb) {
    __shared__ float lg[BSZ][NEXP];
    int tid = threadIdx.x;
    if (tid < BSZ * NEXP) {
        int b = tid / NEXP, e = tid % NEXP;
        const float* w = rW + e * C;
        const float* s = g_S + b * C;
        float dot = 0.f;
        for (int c = 0; c < C; c++) dot += w[c] * s[c];
        float inv = rbs[e] * rsqrtf(1.0f + 1e-5f);
        lg[b][e] = (dot * (1.0f / (float)NCOL) + rb[e]) * inv + rbb[e];
    }
    __syncthreads();
    if (tid < BSZ) {
        int b = tid;
        int i0 = 0; float l0 = lg[b][0];
        for (int e = 1; e < NEXP; e++) if (lg[b][e] > l0) { l0 = lg[b][e]; i0 = e; }
        int i1 = -1; float l1 = -3.4e38f;
        for (int e = 0; e < NEXP; e++) if (e != i0 && lg[b][e] > l1) { l1 = lg[b][e]; i1 = e; }
        float e1 = expf(l1 - l0);
        float denom = 1.0f + e1;
        g_pair_e[2 * b]     = i0;  g_pair_w[2 * b]     = 1.0f / denom;
        g_pair_e[2 * b + 1] = i1;  g_pair_w[2 * b + 1] = e1 / denom;
    }
}

// ---------------- kernel: expert stage (templated stage 1/2) ----------------
// GEMM per pair: out[o, n] = sum_c W[e][o][c] * spike[c, n],  n = hw*4 + t
// STAGE 1: spikes = lif(x, tau_e); epilogue h1 = x + alpha*g + beta  -> g_H1
// STAGE 2: spikes = lif(h1, tau_e); epilogue y = h1 + alpha*g + beta; out += w_p * y
template<int STAGE>
__global__ __launch_bounds__(NTHREADS, 2)
void expert_kernel(const float* __restrict__ x,
                   const float* __restrict__ Wg,
                   const float* __restrict__ bg,
                   const float* __restrict__ bnsg,
                   const float* __restrict__ bnbg,
                   float* __restrict__ outp) {
    const int p  = blockIdx.z;
    const int b  = p >> 1;
    const int e  = g_pair_e[p];
    const float tau = 1.5f + (float)e * (2.5f / 7.0f);

    const int m0  = blockIdx.y * BM;
    const int n0  = blockIdx.x * BN;
    const int hw0 = n0 >> 2;

    __shared__ float As[BM][BK + 4];   // [m][k], pitch 36 words -> conflict-free frags
    __shared__ float Bs[BK][BN + 4];   // [k][n], pitch 132 words -> conflict-free frags

    const int tid  = threadIdx.x;
    const int lane = tid & 31;
    const int warp = tid >> 5;
    const int wm = (warp >> 1) * 32;   // 4 warps along M
    const int wn = (warp & 1) * 64;    // 2 warps along N

    float acc[2][8][4];
#pragma unroll
    for (int mi = 0; mi < 2; mi++)
#pragma unroll
        for (int ni = 0; ni < 8; ni++)
#pragma unroll
            for (int k = 0; k < 4; k++) acc[mi][ni][k] = 0.f;

    const float* Wrow = Wg + (size_t)e * C * C;
    const int pc  = tid >> 3;          // c_local 0..31
    const int phw = (tid & 7) * 4;     // hw_local base (4 per thread)

    for (int kc = 0; kc < C; kc += BK) {
        __syncthreads();  // protect smem from previous iteration's readers
        // ---- A tile: W[e][m0..m0+128][kc..kc+32], tf32-rounded ----
#pragma unroll
        for (int it = 0; it < 4; it++) {
            int idx = tid + it * NTHREADS;
            int r  = idx >> 3;
            int c4 = (idx & 7) * 4;
            float4 wv = *(const float4*)(Wrow + (size_t)(m0 + r) * C + kc + c4);
            As[r][c4 + 0] = __uint_as_float(f2tf32(wv.x));
            As[r][c4 + 1] = __uint_as_float(f2tf32(wv.y));
            As[r][c4 + 2] = __uint_as_float(f2tf32(wv.z));
            As[r][c4 + 3] = __uint_as_float(f2tf32(wv.w));
        }
        // ---- B tile: spikes via fused LIF (thread owns 1 c x 4 hw x all t) ----
        {
            int c = kc + pc;
            float4 in[4];
            if (STAGE == 1) {
#pragma unroll
                for (int t = 0; t < T; t++)   // in[t] = 4 hw values at time t
                    in[t] = *(const float4*)(x + (((size_t)t * BSZ + b) * C + c) * HW + hw0 + phw);
            } else {
                const float* hbase = g_H1 + (((size_t)p * C + c) * HW + hw0 + phw) * T;
#pragma unroll
                for (int j = 0; j < 4; j++)   // in[j] = 4 t values at hw j
                    in[j] = *(const float4*)(hbase + j * T);
            }
#pragma unroll
            for (int j = 0; j < 4; j++) {
                float v = 0.f;
                float s[T];
#pragma unroll
                for (int t = 0; t < T; t++) {
                    float xv = (STAGE == 1) ? ((const float*)&in[t])[j]
                                            : ((const float*)&in[j])[t];
                    v = v + (xv - v) / tau;
                    float sp = (v >= 1.0f) ? 1.f : 0.f;
                    s[t] = sp;
                    v *= (1.f - sp);
                }
                *(float4*)&Bs[pc][(phw + j) * 4] = make_float4(s[0], s[1], s[2], s[3]);
            }
        }
        __syncthreads();
        // ---- mma over the 32-wide k chunk ----
#pragma unroll
        for (int kk = 0; kk < BK; kk += 8) {
            uint32_t afr[2][4], bfr[8][2];
#pragma unroll
            for (int mi = 0; mi < 2; mi++) {
                int r  = wm + mi * 16 + (lane >> 2);
                int cA = kk + (lane & 3);
                afr[mi][0] = __float_as_uint(As[r][cA]);
                afr[mi][1] = __float_as_uint(As[r + 8][cA]);
                afr[mi][2] = __float_as_uint(As[r][cA + 4]);
                afr[mi][3] = __float_as_uint(As[r + 8][cA + 4]);
            }
#pragma unroll
            for (int ni = 0; ni < 8; ni++) {
                int col = wn + ni * 8 + (lane >> 2);
                int rB  = kk + (lane & 3);
                bfr[ni][0] = __float_as_uint(Bs[rB][col]);
                bfr[ni][1] = __float_as_uint(Bs[rB + 4][col]);
            }
#pragma unroll
            for (int mi = 0; mi < 2; mi++)
#pragma unroll
                for (int ni = 0; ni < 8; ni++)
                    asm volatile(
                        "mma.sync.aligned.m16n8k8.row.col.f32.tf32.tf32.f32 "
                        "{%0,%1,%2,%3}, {%4,%5,%6,%7}, {%8,%9}, {%0,%1,%2,%3};"
                        : "+f"(acc[mi][ni][0]), "+f"(acc[mi][ni][1]),
                          "+f"(acc[mi][ni][2]), "+f"(acc[mi][ni][3])
                        : "r"(afr[mi][0]), "r"(afr[mi][1]), "r"(afr[mi][2]), "r"(afr[mi][3]),
                          "r"(bfr[ni][0]), "r"(bfr[ni][1]));
        }
    }

    // ---- epilogue ----
    const float pw   = g_pair_w[p];
    const float rinv = rsqrtf(1.0f + 1e-5f);
#pragma unroll
    for (int mi = 0; mi < 2; mi++) {
#pragma unroll
        for (int half = 0; half < 2; half++) {
            int o = m0 + wm + mi * 16 + (lane >> 2) + half * 8;
            float alpha = bnsg[e * C + o] * rinv;
            float beta  = bg[e * C + o] * alpha + bnbg[e * C + o];
#pragma unroll
            for (int ni = 0; ni < 8; ni++) {
#pragma unroll
                for (int cc = 0; cc < 2; cc++) {
                    float g = acc[mi][ni][half * 2 + cc];
                    int n  = n0 + wn + ni * 8 + (lane & 3) * 2 + cc;
                    int t  = n & 3;
                    int hw = n >> 2;
                    float val = g * alpha + beta;
                    size_t hidx = (((size_t)p * C + o) * HW + hw) * T + t;
                    size_t xidx = (((size_t)t * BSZ + b) * C + o) * HW + hw;
                    if (STAGE == 1) {
                        g_H1[hidx] = x[xidx] + val;   // residual from x
                    } else {
                        float y = g_H1[hidx] + val;   // residual from h1
                        atomicAdd(&outp[xidx], pw * y);
                    }
                }
            }
        }
    }
}

// ---------------- launcher ----------------
extern "C" void kernel_launch(void* const* d_in, const int* in_sizes, int n_in,
                              void* d_out, int out_size) {
    const float* x   = (const float*)d_in[0];
    const float* rW  = (const float*)d_in[1];
    const float* rb  = (const float*)d_in[2];
    const float* rbs = (const float*)d_in[3];
    const float* rbb = (const float*)d_in[4];
    const float* W1  = (const float*)d_in[5];
    const float* b1  = (const float*)d_in[6];
    const float* s1  = (const float*)d_in[7];
    const float* bb1 = (const float*)d_in[8];
    const float* W2  = (const float*)d_in[9];
    const float* b2  = (const float*)d_in[10];
    const float* s2  = (const float*)d_in[11];
    const float* bb2 = (const float*)d_in[12];
    float* out = (float*)d_out;

    // out_size = T*B*C*H*W = 6291456 floats = 1572864 float4
    zero_kernel<<<6144, 256>>>((float4*)out);
    router_s_kernel<<<BSZ * C, 256>>>(x);
    routing_kernel<<<1, 128>>>(rW, rb, rbs, rbb);
    dim3 grid(NCOL / BN, C / BM, BSZ * 2);   // (8, 3, 32)
    expert_kernel<1><<<grid, NTHREADS>>>(x, W1, b1, s1, bb1, out);
    expert_kernel<2><<<grid, NTHREADS>>>(x, W2, b2, s2, bb2, out);
}

// round 5
// speedup vs baseline: 1.0924x; 1.0924x over previous
#include <cuda_runtime.h>
#include <cstdint>

#define T 4
#define BSZ 16
#define C 384
#define HW 256
#define NEXP 8
#define NCOL 1024   // T*HW columns, n = hw*4 + t
#define BM 128
#define BN 128
#define BK 32
#define NK (C / BK) // 12
#define NTHREADS 256
#define APITCH 36   // BK+4, row bytes 144 (16B-aligned)
#define BPITCH 132  // BN+4, row bytes 528 (16B-aligned)
#define SMEM_FLOATS (2 * BM * APITCH + 2 * BK * BPITCH)   // 17664
#define SMEM_BYTES  (SMEM_FLOATS * 4)                     // 70656

// ---------------- device scratch (no allocations allowed) ----------------
__device__ float g_S[BSZ * C];
__device__ int   g_pair_e[BSZ * 2];
__device__ float g_pair_w[BSZ * 2];
__device__ float g_H1[(size_t)32 * C * HW * T];   // h1 scratch [p][c][hw][t]
__device__ float g_SP[(size_t)32 * C * NCOL];     // float spikes [p][c][n], reused per stage

// ---------------- helpers ----------------
__device__ __forceinline__ uint32_t f2tf32(float f) {
    uint32_t r;
    asm("cvt.rna.tf32.f32 %0, %1;" : "=r"(r) : "f"(f));
    return r;
}
__device__ __forceinline__ float expert_tau(int e) {
    return 1.5f + (float)e * (2.5f / 7.0f);
}
__device__ __forceinline__ void cp_async16(uint32_t smem_addr, const void* gptr) {
    asm volatile("cp.async.cg.shared.global [%0], [%1], 16;\n" :: "r"(smem_addr), "l"(gptr));
}

// ---------------- kernel: zero output ----------------
__global__ void zero_kernel(float4* out) {
    size_t i = (size_t)blockIdx.x * blockDim.x + threadIdx.x;
    out[i] = make_float4(0.f, 0.f, 0.f, 0.f);
}

// ---------------- kernel: router S[b,c] = sum_{t,hw} spike(lif(x, tau=2)) ----------------
__global__ void router_s_kernel(const float* __restrict__ x) {
    int bc = blockIdx.x;
    int b = bc / C, c = bc % C;
    int hw = threadIdx.x;
    const float* px = x + (((size_t)b) * C + c) * HW + hw;
    float v = 0.f, cnt = 0.f;
#pragma unroll
    for (int t = 0; t < T; t++) {
        float xv = px[(size_t)t * BSZ * C * HW];
        v = v + (xv - v) / 2.0f;
        float s = (v >= 1.0f) ? 1.f : 0.f;
        cnt += s;
        v = v * (1.f - s);
    }
    __shared__ float red[256];
    red[hw] = cnt;
    __syncthreads();
    for (int o = 128; o > 0; o >>= 1) {
        if (hw < o) red[hw] += red[hw + o];
        __syncthreads();
    }
    if (hw == 0) g_S[bc] = red[0];
}

// ---------------- kernel: logits -> softmax -> top2 -> pair list ----------------
__global__ void routing_kernel(const float* __restrict__ rW, const float* __restrict__ rb,
                               const float* __restrict__ rbs, const float* __restrict__ rbb) {
    __shared__ float lg[BSZ][NEXP];
    int tid = threadIdx.x;
    if (tid < BSZ * NEXP) {
        int b = tid / NEXP, e = tid % NEXP;
        const float* w = rW + e * C;
        const float* s = g_S + b * C;
        float dot = 0.f;
        for (int c = 0; c < C; c++) dot += w[c] * s[c];
        float inv = rbs[e] * rsqrtf(1.0f + 1e-5f);
        lg[b][e] = (dot * (1.0f / (float)NCOL) + rb[e]) * inv + rbb[e];
    }
    __syncthreads();
    if (tid < BSZ) {
        int b = tid;
        int i0 = 0; float l0 = lg[b][0];
        for (int e = 1; e < NEXP; e++) if (lg[b][e] > l0) { l0 = lg[b][e]; i0 = e; }
        int i1 = -1; float l1 = -3.4e38f;
        for (int e = 0; e < NEXP; e++) if (e != i0 && lg[b][e] > l1) { l1 = lg[b][e]; i1 = e; }
        float e1 = expf(l1 - l0);
        float denom = 1.0f + e1;
        g_pair_e[2 * b]     = i0;  g_pair_w[2 * b]     = 1.0f / denom;
        g_pair_e[2 * b + 1] = i1;  g_pair_w[2 * b + 1] = e1 / denom;
    }
}

// ---------------- kernel: float spikes -> g_SP[p][c][n], n = hw*4+t ----------------
// Exactly the round-3 in-GEMM LIF tile code, relocated. One thread = (p, c, 4 hw).
template<int STAGE>
__global__ void spike_kernel(const float* __restrict__ x) {
    int gid = blockIdx.x * blockDim.x + threadIdx.x;   // 0 .. 32*C*64-1
    int q = gid & 63;                  // hw group: hw0 = q*4
    int c = (gid >> 6) % C;
    int p = gid / (C * 64);
    int b = p >> 1;
    const float tau = expert_tau(g_pair_e[p]);
    int hw0 = q * 4;
    float* dst = g_SP + ((size_t)p * C + c) * NCOL + hw0 * 4;
    if (STAGE == 1) {
        float4 in[T];
#pragma unroll
        for (int t = 0; t < T; t++)   // in[t] = 4 hw values at time t
            in[t] = *(const float4*)(x + (((size_t)t * BSZ + b) * C + c) * HW + hw0);
#pragma unroll
        for (int j = 0; j < 4; j++) {
            float v = 0.f;
            float s[T];
#pragma unroll
            for (int t = 0; t < T; t++) {
                float xv = ((const float*)&in[t])[j];
                v = v + (xv - v) / tau;
                float sp = (v >= 1.0f) ? 1.f : 0.f;
                s[t] = sp;
                v *= (1.f - sp);
            }
            *(float4*)(dst + j * 4) = make_float4(s[0], s[1], s[2], s[3]);
        }
    } else {
        const float* hb = g_H1 + (((size_t)p * C + c) * HW + hw0) * T;
#pragma unroll
        for (int j = 0; j < 4; j++) {
            float4 a = *(const float4*)(hb + j * T);   // 4 t values, contiguous
            float v = 0.f;
            float s[T];
#pragma unroll
            for (int t = 0; t < T; t++) {
                float xv = ((const float*)&a)[t];
                v = v + (xv - v) / tau;
                float sp = (v >= 1.0f) ? 1.f : 0.f;
                s[t] = sp;
                v *= (1.f - sp);
            }
            *(float4*)(dst + j * 4) = make_float4(s[0], s[1], s[2], s[3]);
        }
    }
}

// ---------------- kernel: expert GEMM stage ----------------
// out[o,n] = sum_c W[e][o][c] * g_SP[p][c][n]; A and B double-buffered via cp.async.
template<int STAGE>
__global__ __launch_bounds__(NTHREADS, 2)
void expert_kernel(const float* __restrict__ x,
                   const float* __restrict__ Wg,
                   const float* __restrict__ bg,
                   const float* __restrict__ bnsg,
                   const float* __restrict__ bnbg,
                   float* __restrict__ outp) {
    extern __shared__ float sm[];
    float (*As)[BM][APITCH] = (float (*)[BM][APITCH])sm;
    float (*Bs)[BK][BPITCH] = (float (*)[BK][BPITCH])(sm + 2 * BM * APITCH);

    const int p = blockIdx.z;
    const int b = p >> 1;
    const int e = g_pair_e[p];

    const int m0 = blockIdx.y * BM;
    const int n0 = blockIdx.x * BN;

    const int tid  = threadIdx.x;
    const int lane = tid & 31;
    const int warp = tid >> 5;
    const int wm = (warp >> 1) * 32;   // 4 warps along M
    const int wn = (warp & 1) * 64;    // 2 warps along N

    float acc[2][8][4];
#pragma unroll
    for (int mi = 0; mi < 2; mi++)
#pragma unroll
        for (int ni = 0; ni < 8; ni++)
#pragma unroll
            for (int k = 0; k < 4; k++) acc[mi][ni][k] = 0.f;

    const float* Wrow = Wg + (size_t)e * C * C + (size_t)m0 * C;
    const float* Brow = g_SP + (size_t)p * C * NCOL + n0;

    auto copy_tiles = [&](int chunk, int s) {
        // A: 128 rows x 32 cols of W
#pragma unroll
        for (int it = 0; it < 4; it++) {
            int idx = tid + it * NTHREADS;     // 0..1023
            int r = idx >> 3;
            int c4 = (idx & 7) << 2;
            cp_async16((uint32_t)__cvta_generic_to_shared(&As[s][r][c4]),
                       Wrow + chunk * BK + (size_t)r * C + c4);
        }
        // B: 32 rows (c) x 128 cols (n) of spikes
#pragma unroll
        for (int it = 0; it < 4; it++) {
            int idx = tid + it * NTHREADS;     // 0..1023
            int r = idx >> 5;                  // 0..31
            int c4 = (idx & 31) << 2;          // 0..124
            cp_async16((uint32_t)__cvta_generic_to_shared(&Bs[s][r][c4]),
                       Brow + (size_t)(chunk * BK + r) * NCOL + c4);
        }
    };

    copy_tiles(0, 0);
    asm volatile("cp.async.commit_group;\n" ::);

    for (int ki = 0; ki < NK; ki++) {
        asm volatile("cp.async.wait_group 0;\n" ::);
        __syncthreads();
        if (ki + 1 < NK) copy_tiles(ki + 1, (ki + 1) & 1);
        asm volatile("cp.async.commit_group;\n" ::);

        const int s = ki & 1;
#pragma unroll
        for (int kk = 0; kk < BK; kk += 8) {
            uint32_t afr[2][4], bfr[8][2];
            int cA = kk + (lane & 3);
#pragma unroll
            for (int mi = 0; mi < 2; mi++) {
                int r = wm + mi * 16 + (lane >> 2);
                afr[mi][0] = f2tf32(As[s][r][cA]);
                afr[mi][1] = f2tf32(As[s][r + 8][cA]);
                afr[mi][2] = f2tf32(As[s][r][cA + 4]);
                afr[mi][3] = f2tf32(As[s][r + 8][cA + 4]);
            }
#pragma unroll
            for (int ni = 0; ni < 8; ni++) {
                int col = wn + ni * 8 + (lane >> 2);
                int rB  = kk + (lane & 3);
                bfr[ni][0] = __float_as_uint(Bs[s][rB][col]);      // spikes are exact {0,1}
                bfr[ni][1] = __float_as_uint(Bs[s][rB + 4][col]);
            }
#pragma unroll
            for (int mi = 0; mi < 2; mi++)
#pragma unroll
                for (int ni = 0; ni < 8; ni++)
                    asm volatile(
                        "mma.sync.aligned.m16n8k8.row.col.f32.tf32.tf32.f32 "
                        "{%0,%1,%2,%3}, {%4,%5,%6,%7}, {%8,%9}, {%0,%1,%2,%3};"
                        : "+f"(acc[mi][ni][0]), "+f"(acc[mi][ni][1]),
                          "+f"(acc[mi][ni][2]), "+f"(acc[mi][ni][3])
                        : "r"(afr[mi][0]), "r"(afr[mi][1]), "r"(afr[mi][2]), "r"(afr[mi][3]),
                          "r"(bfr[ni][0]), "r"(bfr[ni][1]));
        }
    }

    // ---- epilogue (round-3 verbatim) ----
    const float pw   = g_pair_w[p];
    const float rinv = rsqrtf(1.0f + 1e-5f);
#pragma unroll
    for (int mi = 0; mi < 2; mi++) {
#pragma unroll
        for (int half = 0; half < 2; half++) {
            int o = m0 + wm + mi * 16 + (lane >> 2) + half * 8;
            float alpha = bnsg[e * C + o] * rinv;
            float beta  = bg[e * C + o] * alpha + bnbg[e * C + o];
#pragma unroll
            for (int ni = 0; ni < 8; ni++) {
#pragma unroll
                for (int cc = 0; cc < 2; cc++) {
                    float g = acc[mi][ni][half * 2 + cc];
                    int n  = n0 + wn + ni * 8 + (lane & 3) * 2 + cc;
                    int t  = n & 3;
                    int hw = n >> 2;
                    float val = g * alpha + beta;
                    size_t hidx = (((size_t)p * C + o) * HW + hw) * T + t;
                    size_t xidx = (((size_t)t * BSZ + b) * C + o) * HW + hw;
                    if (STAGE == 1) {
                        g_H1[hidx] = x[xidx] + val;   // residual from x
                    } else {
                        float y = g_H1[hidx] + val;   // residual from h1
                        atomicAdd(&outp[xidx], pw * y);
                    }
                }
            }
        }
    }
}

// ---------------- launcher ----------------
extern "C" void kernel_launch(void* const* d_in, const int* in_sizes, int n_in,
                              void* d_out, int out_size) {
    const float* x   = (const float*)d_in[0];
    const float* rW  = (const float*)d_in[1];
    const float* rb  = (const float*)d_in[2];
    const float* rbs = (const float*)d_in[3];
    const float* rbb = (const float*)d_in[4];
    const float* W1  = (const float*)d_in[5];
    const float* b1  = (const float*)d_in[6];
    const float* s1  = (const float*)d_in[7];
    const float* bb1 = (const float*)d_in[8];
    const float* W2  = (const float*)d_in[9];
    const float* b2  = (const float*)d_in[10];
    const float* s2  = (const float*)d_in[11];
    const float* bb2 = (const float*)d_in[12];
    float* out = (float*)d_out;

    cudaFuncSetAttribute(expert_kernel<1>, cudaFuncAttributeMaxDynamicSharedMemorySize, SMEM_BYTES);
    cudaFuncSetAttribute(expert_kernel<2>, cudaFuncAttributeMaxDynamicSharedMemorySize, SMEM_BYTES);

    zero_kernel<<<6144, 256>>>((float4*)out);
    router_s_kernel<<<BSZ * C, 256>>>(x);
    routing_kernel<<<1, 128>>>(rW, rb, rbs, rbb);

    const int spike_blocks = (32 * C * 64) / 256;   // 3072
    dim3 grid(NCOL / BN, C / BM, BSZ * 2);          // (8, 3, 32)

    spike_kernel<1><<<spike_blocks, 256>>>(x);
    expert_kernel<1><<<grid, NTHREADS, SMEM_BYTES>>>(x, W1, b1, s1, bb1, out);
    spike_kernel<2><<<spike_blocks, 256>>>(x);
    expert_kernel<2><<<grid, NTHREADS, SMEM_BYTES>>>(x, W2, b2, s2, bb2, out);
}

// round 8
// speedup vs baseline: 1.2523x; 1.1464x over previous
#include <cuda_runtime.h>
#include <cstdint>

#define T 4
#define BSZ 16
#define C 384
#define HW 256
#define NEXP 8
#define NCOL 1024   // T*HW columns, n = hw*4 + t
#define BM 128
#define BN 128
#define BK 32
#define NK 12       // C / BK
#define NTHREADS 256
#define ACHUNK 4608 // padded A chunk floats in smem (4 wmid * 32 lane * 36)
#define BCHUNK 4224 // padded B chunk floats in smem (32 c * 132)
#define SMEM_FLOATS (2 * ACHUNK + 2 * BCHUNK)
#define SMEM_BYTES  (SMEM_FLOATS * 4)   // 70656

// ---------------- device scratch (no allocations allowed) ----------------
__device__ float g_S[BSZ * C];
__device__ int   g_pair_e[BSZ * 2];
__device__ float g_pair_w[BSZ * 2];
__device__ float g_H1[(size_t)32 * C * HW * T];     // h1 scratch [p][c][hw][t]
__device__ float g_SPg[(size_t)32 * C * NCOL];      // spikes [p][c][j=n%8][w=n/8]
__device__ float g_WT[(size_t)16 * 36 * 4096];      // fragment-major W [stage*8+e][mb*12+kc][4096]

// ---------------- helpers ----------------
__device__ __forceinline__ uint32_t f2tf32(float f) {
    uint32_t r;
    asm("cvt.rna.tf32.f32 %0, %1;" : "=r"(r) : "f"(f));
    return r;
}
__device__ __forceinline__ float expert_tau(int e) {
    return 1.5f + (float)e * (2.5f / 7.0f);
}
__device__ __forceinline__ void cp_async16(uint32_t smem_addr, const void* gptr) {
    asm volatile("cp.async.cg.shared.global [%0], [%1], 16;\n" :: "r"(smem_addr), "l"(gptr));
}

// ---------------- kernel: transform W into mma-fragment-major layout ----------------
// dst chunk layout [wmid 4][lane 32][kki 4][mi 2][q 4], q = half_k*2 + half_m
__global__ void wtrans_kernel(const float* __restrict__ W, int eoff) {
    int gid = blockIdx.x * 256 + threadIdx.x;       // 0 .. 8*384*384-1
    int k = gid % C;
    int m = (gid / C) % C;
    int e = gid / (C * C);
    float w = W[gid];
    int mb = m >> 7, rm = m & 127, kc = k >> 5, rk = k & 31;
    int kki = rk >> 3, pos = rk & 7, lk = pos & 3, hk = pos >> 2;
    int wmid = rm >> 5, rr = rm & 31, mi = rr >> 4, rem = rr & 15, hm = rem >> 3, l4 = rem & 7;
    int lane = l4 * 4 + lk;
    int q = hk * 2 + hm;
    size_t dst = ((size_t)(eoff + e) * 36 + mb * 12 + kc) * 4096
               + ((size_t)(wmid * 32 + lane) * 4 + kki) * 8 + mi * 4 + q;
    g_WT[dst] = w;
}

// ---------------- kernel: router S[b,c] ----------------
__global__ void router_s_kernel(const float* __restrict__ x) {
    int bc = blockIdx.x;
    int b = bc / C, c = bc % C;
    int hw = threadIdx.x;
    const float* px = x + (((size_t)b) * C + c) * HW + hw;
    float v = 0.f, cnt = 0.f;
#pragma unroll
    for (int t = 0; t < T; t++) {
        float xv = px[(size_t)t * BSZ * C * HW];
        v = v + (xv - v) / 2.0f;
        float s = (v >= 1.0f) ? 1.f : 0.f;
        cnt += s;
        v = v * (1.f - s);
    }
#pragma unroll
    for (int o = 16; o > 0; o >>= 1) cnt += __shfl_down_sync(0xffffffffu, cnt, o);
    __shared__ float red[8];
    if ((hw & 31) == 0) red[hw >> 5] = cnt;
    __syncthreads();
    if (hw < 8) {
        float vv = red[hw];
#pragma unroll
        for (int o = 4; o > 0; o >>= 1) vv += __shfl_down_sync(0xffu, vv, o);
        if (hw == 0) g_S[bc] = vv;
    }
}

// ---------------- kernel: logits -> softmax -> top2 -> pair list ----------------
__global__ void routing_kernel(const float* __restrict__ rW, const float* __restrict__ rb,
                               const float* __restrict__ rbs, const float* __restrict__ rbb) {
    __shared__ float lg[BSZ][NEXP];
    int tid = threadIdx.x;
    if (tid < BSZ * NEXP) {
        int b = tid / NEXP, e = tid % NEXP;
        const float* w = rW + e * C;
        const float* s = g_S + b * C;
        float dot = 0.f;
        for (int c = 0; c < C; c++) dot += w[c] * s[c];
        float inv = rbs[e] * rsqrtf(1.0f + 1e-5f);
        lg[b][e] = (dot * (1.0f / (float)NCOL) + rb[e]) * inv + rbb[e];
    }
    __syncthreads();
    if (tid < BSZ) {
        int b = tid;
        int i0 = 0; float l0 = lg[b][0];
        for (int e = 1; e < NEXP; e++) if (lg[b][e] > l0) { l0 = lg[b][e]; i0 = e; }
        int i1 = -1; float l1 = -3.4e38f;
        for (int e = 0; e < NEXP; e++) if (e != i0 && lg[b][e] > l1) { l1 = lg[b][e]; i1 = e; }
        float e1 = expf(l1 - l0);
        float denom = 1.0f + e1;
        g_pair_e[2 * b]     = i0;  g_pair_w[2 * b]     = 1.0f / denom;
        g_pair_e[2 * b + 1] = i1;  g_pair_w[2 * b + 1] = e1 / denom;
    }
}

// ---------------- kernel: stage-1 spikes (both pairs of batch b, read x once) ----------------
// thread = (b, c, w); hw = 2w, 2w+1; writes g_SPg[p][c][j][w], j = (hw&1)*4 + t
__global__ void spike1_kernel(const float* __restrict__ x) {
    int gid = blockIdx.x * 256 + threadIdx.x;       // 0 .. 16*384*128-1
    int w = gid & 127;
    int c = (gid >> 7) % C;
    int b = gid / (C * 128);
    float tau0 = expert_tau(g_pair_e[2 * b]);
    float tau1 = expert_tau(g_pair_e[2 * b + 1]);
    float2 in[T];
#pragma unroll
    for (int t = 0; t < T; t++)
        in[t] = *(const float2*)(x + (((size_t)t * BSZ + b) * C + c) * HW + 2 * w);
    float* d0 = g_SPg + ((size_t)(2 * b) * C + c) * NCOL + w;
    float* d1 = g_SPg + ((size_t)(2 * b + 1) * C + c) * NCOL + w;
#pragma unroll
    for (int hwi = 0; hwi < 2; hwi++) {
        float v0 = 0.f, v1 = 0.f;
#pragma unroll
        for (int t = 0; t < T; t++) {
            float xv = hwi ? in[t].y : in[t].x;
            v0 = v0 + (xv - v0) / tau0;
            float s0 = (v0 >= 1.0f) ? 1.f : 0.f;
            d0[(hwi * 4 + t) * 128] = s0;
            v0 *= (1.f - s0);
            v1 = v1 + (xv - v1) / tau1;
            float s1 = (v1 >= 1.0f) ? 1.f : 0.f;
            d1[(hwi * 4 + t) * 128] = s1;
            v1 *= (1.f - s1);
        }
    }
}

// ---------------- kernel: stage-2 spikes from g_H1 ----------------
__global__ void spike2_kernel() {
    int gid = blockIdx.x * 256 + threadIdx.x;       // 0 .. 32*384*128-1
    int w = gid & 127;
    int c = (gid >> 7) % C;
    int p = gid / (C * 128);
    float tau = expert_tau(g_pair_e[p]);
    const float* hb = g_H1 + (((size_t)p * C + c) * HW + 2 * w) * T;
    float4 a0 = *(const float4*)hb;
    float4 a1 = *(const float4*)(hb + 4);
    float* dst = g_SPg + ((size_t)p * C + c) * NCOL + w;
#pragma unroll
    for (int hwi = 0; hwi < 2; hwi++) {
        float4 a = hwi ? a1 : a0;
        float v = 0.f;
#pragma unroll
        for (int t = 0; t < T; t++) {
            float xv = ((const float*)&a)[t];
            v = v + (xv - v) / tau;
            float s = (v >= 1.0f) ? 1.f : 0.f;
            dst[(hwi * 4 + t) * 128] = s;
            v *= (1.f - s);
        }
    }
}

// ---------------- kernel: expert GEMM stage ----------------
// STAGE 1: z = p (32), K = 384, acc = alpha*g, h1 = x + acc + beta -> g_H1
// STAGE 2: z = b (16), K = 2*384 (both pairs), acc = sum_p pw*alpha*g,
//          out = acc + sum_p pw*(h1_p + beta_p)  (plain stores)
template<int STAGE>
__global__ __launch_bounds__(NTHREADS, 2)
void expert_kernel(const float* __restrict__ x,
                   const float* __restrict__ bg,
                   const float* __restrict__ bnsg,
                   const float* __restrict__ bnbg,
                   float* __restrict__ outp) {
    extern __shared__ float sm[];
    float* Asm = sm;                 // 2 * ACHUNK
    float* Bsm = sm + 2 * ACHUNK;    // 2 * BCHUNK

    const int mb = blockIdx.y;
    const int m0 = mb * BM;
    const int n0 = blockIdx.x * BN;
    const int w0 = blockIdx.x * 16;

    const int tid  = threadIdx.x;
    const int lane = tid & 31;
    const int warp = tid >> 5;
    const int wmid = warp >> 1;
    const int wm   = wmid * 32;
    const int wn   = (warp & 1) * 64;
    const int wn8  = (warp & 1) * 8;
    const int l4   = lane >> 2;

    const int nph   = (STAGE == 1) ? 1 : 2;
    const int pbase = (STAGE == 1) ? blockIdx.z : 2 * blockIdx.z;
    const int b     = (STAGE == 1) ? (pbase >> 1) : blockIdx.z;
    const int eoff  = (STAGE == 1) ? 0 : 8;
    const int KT    = nph * NK;
    const float rinv = rsqrtf(1.0f + 1e-5f);

    int   pe[2];
    float ppw[2];
    float scl[2][4];
#pragma unroll
    for (int ph = 0; ph < 2; ph++) {
        if (ph >= nph) break;
        int p = pbase + ph;
        pe[ph]  = g_pair_e[p];
        ppw[ph] = g_pair_w[p];
        float mult = (STAGE == 1) ? 1.0f : ppw[ph];
#pragma unroll
        for (int mi = 0; mi < 2; mi++)
#pragma unroll
            for (int hm = 0; hm < 2; hm++) {
                int o = m0 + wm + mi * 16 + hm * 8 + l4;
                scl[ph][mi * 2 + hm] = bnsg[pe[ph] * C + o] * rinv * mult;
            }
    }

    float acc[2][8][4];
#pragma unroll
    for (int mi = 0; mi < 2; mi++)
#pragma unroll
        for (int ni = 0; ni < 8; ni++)
#pragma unroll
            for (int k = 0; k < 4; k++) acc[mi][ni][k] = 0.f;

    auto copy_tiles = [&](int kt, int s) {
        int ph = (STAGE == 2 && kt >= NK) ? 1 : 0;
        int kc = kt - ph * NK;
        const float* Asrc = g_WT + (((size_t)(eoff + pe[ph]) * 3 + mb) * NK + kc) * 4096;
        float* Asd = Asm + s * ACHUNK;
#pragma unroll
        for (int it = 0; it < 4; it++) {
            int idx = tid + it * NTHREADS;     // 0..1023
            int p4 = idx >> 3, sub = idx & 7;
            cp_async16((uint32_t)__cvta_generic_to_shared(
                           Asd + (p4 >> 5) * 1152 + (p4 & 31) * 36 + sub * 4),
                       Asrc + (size_t)p4 * 32 + sub * 4);
        }
        const float* Bsrc = g_SPg + ((size_t)(pbase + ph) * C + kc * 32) * NCOL + w0;
        float* Bsd = Bsm + s * BCHUNK;
#pragma unroll
        for (int it = 0; it < 4; it++) {
            int idx = tid + it * NTHREADS;     // 0..1023
            int cl = idx >> 5, j = (idx >> 2) & 7, sub = idx & 3;
            cp_async16((uint32_t)__cvta_generic_to_shared(
                           Bsd + cl * 132 + j * 16 + sub * 4),
                       Bsrc + ((size_t)cl * 8 + j) * 128 + sub * 4);
        }
    };

    copy_tiles(0, 0);
    asm volatile("cp.async.commit_group;\n" ::);

    for (int kt = 0; kt < KT; kt++) {
        asm volatile("cp.async.wait_group 0;\n" ::);
        __syncthreads();
        if (kt + 1 < KT) copy_tiles(kt + 1, (kt + 1) & 1);
        asm volatile("cp.async.commit_group;\n" ::);

        const int s  = kt & 1;
        const int ph = (STAGE == 2 && kt >= NK) ? 1 : 0;
        const float* Ab = Asm + s * ACHUNK + wmid * 1152 + lane * 36;
        const float* Bb = Bsm + s * BCHUNK + (lane & 3) * 132 + l4 * 16 + wn8;
        const float* sc = scl[ph];

#pragma unroll
        for (int kki = 0; kki < 4; kki++) {
            float4 ra0 = *(const float4*)(Ab + kki * 8);
            float4 ra1 = *(const float4*)(Ab + kki * 8 + 4);
            uint32_t afr[2][4];
            afr[0][0] = f2tf32(ra0.x * sc[0]);
            afr[0][1] = f2tf32(ra0.y * sc[1]);
            afr[0][2] = f2tf32(ra0.z * sc[0]);
            afr[0][3] = f2tf32(ra0.w * sc[1]);
            afr[1][0] = f2tf32(ra1.x * sc[2]);
            afr[1][1] = f2tf32(ra1.y * sc[3]);
            afr[1][2] = f2tf32(ra1.z * sc[2]);
            afr[1][3] = f2tf32(ra1.w * sc[3]);

            const float* br0 = Bb + kki * 8 * 132;
            const float* br1 = br0 + 4 * 132;
            float4 b00 = *(const float4*)br0;
            float4 b01 = *(const float4*)(br0 + 4);
            float4 b10 = *(const float4*)br1;
            float4 b11 = *(const float4*)(br1 + 4);
            float bf0a[8] = {b00.x, b00.y, b00.z, b00.w, b01.x, b01.y, b01.z, b01.w};
            float bf1a[8] = {b10.x, b10.y, b10.z, b10.w, b11.x, b11.y, b11.z, b11.w};

#pragma unroll
            for (int ni = 0; ni < 8; ni++) {
                uint32_t bf0 = __float_as_uint(bf0a[ni]);
                uint32_t bf1 = __float_as_uint(bf1a[ni]);
#pragma unroll
                for (int mi = 0; mi < 2; mi++)
                    asm volatile(
                        "mma.sync.aligned.m16n8k8.row.col.f32.tf32.tf32.f32 "
                        "{%0,%1,%2,%3}, {%4,%5,%6,%7}, {%8,%9}, {%0,%1,%2,%3};"
                        : "+f"(acc[mi][ni][0]), "+f"(acc[mi][ni][1]),
                          "+f"(acc[mi][ni][2]), "+f"(acc[mi][ni][3])
                        : "r"(afr[mi][0]), "r"(afr[mi][1]), "r"(afr[mi][2]), "r"(afr[mi][3]),
                          "r"(bf0), "r"(bf1));
            }
        }
    }

    // ---- epilogue ----
#pragma unroll
    for (int mi = 0; mi < 2; mi++) {
#pragma unroll
        for (int half = 0; half < 2; half++) {
            int o = m0 + wm + mi * 16 + l4 + half * 8;
            if (STAGE == 1) {
                int e = pe[0];
                float alpha = scl[0][mi * 2 + half];   // == bnsg*rinv (mult=1)
                float beta  = bg[e * C + o] * alpha + bnbg[e * C + o];
#pragma unroll
                for (int ni = 0; ni < 8; ni++) {
                    int n  = n0 + wn + ni * 8 + (lane & 3) * 2;
                    int t  = n & 3;
                    int hw = n >> 2;
                    size_t hidx = (((size_t)pbase * C + o) * HW + hw) * T + t;
                    size_t xi0  = (((size_t)t * BSZ + b) * C + o) * HW + hw;
                    size_t xi1  = (((size_t)(t + 1) * BSZ + b) * C + o) * HW + hw;
                    float g0 = acc[mi][ni][half * 2 + 0] + beta;
                    float g1 = acc[mi][ni][half * 2 + 1] + beta;
                    *(float2*)&g_H1[hidx] = make_float2(x[xi0] + g0, x[xi1] + g1);
                }
            } else {
                float a0 = bnsg[pe[0] * C + o] * rinv;
                float a1 = bnsg[pe[1] * C + o] * rinv;
                float be0 = bg[pe[0] * C + o] * a0 + bnbg[pe[0] * C + o];
                float be1 = bg[pe[1] * C + o] * a1 + bnbg[pe[1] * C + o];
#pragma unroll
                for (int ni = 0; ni < 8; ni++) {
                    int n  = n0 + wn + ni * 8 + (lane & 3) * 2;
                    int t  = n & 3;
                    int hw = n >> 2;
                    size_t h0i = (((size_t)(pbase + 0) * C + o) * HW + hw) * T + t;
                    size_t h1i = (((size_t)(pbase + 1) * C + o) * HW + hw) * T + t;
                    float2 h0 = *(const float2*)&g_H1[h0i];
                    float2 h1 = *(const float2*)&g_H1[h1i];
                    size_t xi0 = (((size_t)t * BSZ + b) * C + o) * HW + hw;
                    size_t xi1 = (((size_t)(t + 1) * BSZ + b) * C + o) * HW + hw;
                    outp[xi0] = acc[mi][ni][half * 2 + 0]
                              + ppw[0] * (h0.x + be0) + ppw[1] * (h1.x + be1);
                    outp[xi1] = acc[mi][ni][half * 2 + 1]
                              + ppw[0] * (h0.y + be0) + ppw[1] * (h1.y + be1);
                }
            }
        }
    }
}

// ---------------- launcher ----------------
extern "C" void kernel_launch(void* const* d_in, const int* in_sizes, int n_in,
                              void* d_out, int out_size) {
    const float* x   = (const float*)d_in[0];
    const float* rW  = (const float*)d_in[1];
    const float* rb  = (const float*)d_in[2];
    const float* rbs = (const float*)d_in[3];
    const float* rbb = (const float*)d_in[4];
    const float* W1  = (const float*)d_in[5];
    const float* b1  = (const float*)d_in[6];
    const float* s1  = (const float*)d_in[7];
    const float* bb1 = (const float*)d_in[8];
    const float* W2  = (const float*)d_in[9];
    const float* b2  = (const float*)d_in[10];
    const float* s2  = (const float*)d_in[11];
    const float* bb2 = (const float*)d_in[12];
    float* out = (float*)d_out;

    cudaFuncSetAttribute(expert_kernel<1>, cudaFuncAttributeMaxDynamicSharedMemorySize, SMEM_BYTES);
    cudaFuncSetAttribute(expert_kernel<2>, cudaFuncAttributeMaxDynamicSharedMemorySize, SMEM_BYTES);

    wtrans_kernel<<<(NEXP * C * C) / 256, 256>>>(W1, 0);
    wtrans_kernel<<<(NEXP * C * C) / 256, 256>>>(W2, 8);
    router_s_kernel<<<BSZ * C, 256>>>(x);
    routing_kernel<<<1, 128>>>(rW, rb, rbs, rbb);

    spike1_kernel<<<(BSZ * C * 128) / 256, 256>>>(x);
    dim3 grid1(NCOL / BN, C / BM, 32);
    expert_kernel<1><<<grid1, NTHREADS, SMEM_BYTES>>>(x, b1, s1, bb1, out);

    spike2_kernel<<<(32 * C * 128) / 256, 256>>>();
    dim3 grid2(NCOL / BN, C / BM, 16);
    expert_kernel<2><<<grid2, NTHREADS, SMEM_BYTES>>>(x, b2, s2, bb2, out);
}

// round 9
// speedup vs baseline: 1.3594x; 1.0855x over previous
#include <cuda_runtime.h>
#include <cstdint>

#define T 4
#define BSZ 16
#define C 384
#define HW 256
#define NEXP 8
#define NCOL 1024   // T*HW columns, n = hw*4 + t
#define BM 128
#define BN 128
#define BK 32
#define NK 12       // C / BK
#define NTHREADS 256
#define ACHUNK 4608 // padded A chunk floats in smem (4 wmid * 32 lane * 36)
#define BCHUNK 4224 // padded B chunk floats in smem (32 c * 132)
#define SMEM_FLOATS (2 * ACHUNK + 2 * BCHUNK)
#define SMEM_BYTES  (SMEM_FLOATS * 4)   // 70656

// ---------------- device scratch (no allocations allowed) ----------------
__device__ float g_S[BSZ * C];
__device__ int   g_pair_e[BSZ * 2];
__device__ float g_pair_w[BSZ * 2];
__device__ float g_H1[(size_t)32 * C * HW * T];     // h1 scratch [p][c][hw][t]
__device__ float g_SPg[(size_t)32 * C * NCOL];      // spikes [p][c][j=n%8][w=n/8]
__device__ float g_WT[(size_t)16 * 36 * 4096];      // frag-major, alpha-scaled, tf32-rounded W

// ---------------- helpers ----------------
__device__ __forceinline__ uint32_t f2tf32(float f) {
    uint32_t r;
    asm("cvt.rna.tf32.f32 %0, %1;" : "=r"(r) : "f"(f));
    return r;
}
__device__ __forceinline__ float expert_tau(int e) {
    return 1.5f + (float)e * (2.5f / 7.0f);
}
__device__ __forceinline__ void cp_async16(uint32_t smem_addr, const void* gptr) {
    asm volatile("cp.async.cg.shared.global [%0], [%1], 16;\n" :: "r"(smem_addr), "l"(gptr));
}

// ---------------- kernel: transform W -> fragment-major, alpha-scaled, tf32-rounded ----------------
// chunk layout per (e,mb,kc): [wmid 4][lane 32][kki 4][mi 2][q 4], q = hk*2 + hm
// lane = l4*4 + lk; element = W[e][mb*128+wmid*32+mi*16+hm*8+l4][kc*32+kki*8+hk*4+lk] * alpha(e,m)
// grid 288 (= 8e * 3mb * 12kc), block 256 (= 8 warps: mi,wmid; 32 lanes: l4,kki)
__global__ void wtrans_kernel(const float* __restrict__ W, const float* __restrict__ bnsg, int eoff) {
    const int bid = blockIdx.x;
    const int e  = bid / 36;
    const int mb = (bid / 12) % 3;
    const int kc = bid % 12;
    const int tid  = threadIdx.x;
    const int lane = tid & 31;
    const int warp = tid >> 5;
    const int mi   = warp & 1;
    const int wmid = warp >> 1;
    const int kki  = lane & 3;
    const int l4   = lane >> 2;

    const int m0 = mb * 128 + wmid * 32 + mi * 16 + l4;   // hm=0 row
    const int k0 = kc * 32 + kki * 8;
    const float rinv = rsqrtf(1.0f + 1e-5f);
    const float al0 = bnsg[e * C + m0] * rinv;
    const float al1 = bnsg[e * C + m0 + 8] * rinv;

    const float* src = W + ((size_t)e * C + m0) * C + k0;
    float4 a0 = *(const float4*)src;            // row m0,   k0..k0+3  (hk=0)
    float4 a1 = *(const float4*)(src + 4);      // row m0,   k0+4..+7  (hk=1)
    float4 b0 = *(const float4*)(src + 8 * C);  // row m0+8
    float4 b1 = *(const float4*)(src + 8 * C + 4);

    uint32_t* dstc = (uint32_t*)(g_WT + (((size_t)(eoff + e) * 3 + mb) * NK + kc) * 4096);
#pragma unroll
    for (int lk = 0; lk < 4; lk++) {
        uint4 o;
        o.x = f2tf32((&a0.x)[lk] * al0);   // q=0: (hk0, hm0)
        o.y = f2tf32((&b0.x)[lk] * al1);   // q=1: (hk0, hm1)
        o.z = f2tf32((&a1.x)[lk] * al0);   // q=2: (hk1, hm0)
        o.w = f2tf32((&b1.x)[lk] * al1);   // q=3: (hk1, hm1)
        *(uint4*)(dstc + (size_t)(wmid * 32 + l4 * 4 + lk) * 32 + kki * 8 + mi * 4) = o;
    }
}

// ---------------- kernel: router S[b,c] ----------------
__global__ void router_s_kernel(const float* __restrict__ x) {
    int bc = blockIdx.x;
    int b = bc / C, c = bc % C;
    int hw = threadIdx.x;
    const float* px = x + (((size_t)b) * C + c) * HW + hw;
    float v = 0.f, cnt = 0.f;
#pragma unroll
    for (int t = 0; t < T; t++) {
        float xv = px[(size_t)t * BSZ * C * HW];
        v = v + (xv - v) / 2.0f;
        float s = (v >= 1.0f) ? 1.f : 0.f;
        cnt += s;
        v = v * (1.f - s);
    }
#pragma unroll
    for (int o = 16; o > 0; o >>= 1) cnt += __shfl_down_sync(0xffffffffu, cnt, o);
    __shared__ float red[8];
    if ((hw & 31) == 0) red[hw >> 5] = cnt;
    __syncthreads();
    if (hw < 8) {
        float vv = red[hw];
#pragma unroll
        for (int o = 4; o > 0; o >>= 1) vv += __shfl_down_sync(0xffu, vv, o);
        if (hw == 0) g_S[bc] = vv;
    }
}

// ---------------- kernel: logits -> softmax -> top2 -> pair list (parallel dots) ----------------
// 1024 threads: 8 threads per (b,e) pair, interleaved-coalesced dot + shfl reduce
__global__ void routing_kernel(const float* __restrict__ rW, const float* __restrict__ rb,
                               const float* __restrict__ rbs, const float* __restrict__ rbb) {
    __shared__ float lg[BSZ][NEXP];
    int tid = threadIdx.x;
    int pair = tid >> 3;               // 0..127
    int sl   = tid & 7;
    int b = pair >> 3, e = pair & 7;
    const float* w = rW + e * C;
    const float* s = g_S + b * C;
    float dot = 0.f;
#pragma unroll
    for (int i = 0; i < C / 8; i++) {
        int c = sl + i * 8;
        dot += w[c] * s[c];
    }
#pragma unroll
    for (int o = 4; o > 0; o >>= 1) dot += __shfl_xor_sync(0xffffffffu, dot, o);
    if (sl == 0) {
        float inv = rbs[e] * rsqrtf(1.0f + 1e-5f);
        lg[b][e] = (dot * (1.0f / (float)NCOL) + rb[e]) * inv + rbb[e];
    }
    __syncthreads();
    if (tid < BSZ) {
        int bb = tid;
        int i0 = 0; float l0 = lg[bb][0];
        for (int ee = 1; ee < NEXP; ee++) if (lg[bb][ee] > l0) { l0 = lg[bb][ee]; i0 = ee; }
        int i1 = -1; float l1 = -3.4e38f;
        for (int ee = 0; ee < NEXP; ee++) if (ee != i0 && lg[bb][ee] > l1) { l1 = lg[bb][ee]; i1 = ee; }
        float e1 = expf(l1 - l0);
        float denom = 1.0f + e1;
        g_pair_e[2 * bb]     = i0;  g_pair_w[2 * bb]     = 1.0f / denom;
        g_pair_e[2 * bb + 1] = i1;  g_pair_w[2 * bb + 1] = e1 / denom;
    }
}

// ---------------- kernel: stage-1 spikes (both pairs of batch b, read x once) ----------------
__global__ void spike1_kernel(const float* __restrict__ x) {
    int gid = blockIdx.x * 256 + threadIdx.x;       // 0 .. 16*384*128-1
    int w = gid & 127;
    int c = (gid >> 7) % C;
    int b = gid / (C * 128);
    float tau0 = expert_tau(g_pair_e[2 * b]);
    float tau1 = expert_tau(g_pair_e[2 * b + 1]);
    float2 in[T];
#pragma unroll
    for (int t = 0; t < T; t++)
        in[t] = *(const float2*)(x + (((size_t)t * BSZ + b) * C + c) * HW + 2 * w);
    float* d0 = g_SPg + ((size_t)(2 * b) * C + c) * NCOL + w;
    float* d1 = g_SPg + ((size_t)(2 * b + 1) * C + c) * NCOL + w;
#pragma unroll
    for (int hwi = 0; hwi < 2; hwi++) {
        float v0 = 0.f, v1 = 0.f;
#pragma unroll
        for (int t = 0; t < T; t++) {
            float xv = hwi ? in[t].y : in[t].x;
            v0 = v0 + (xv - v0) / tau0;
            float s0 = (v0 >= 1.0f) ? 1.f : 0.f;
            d0[(hwi * 4 + t) * 128] = s0;
            v0 *= (1.f - s0);
            v1 = v1 + (xv - v1) / tau1;
            float s1 = (v1 >= 1.0f) ? 1.f : 0.f;
            d1[(hwi * 4 + t) * 128] = s1;
            v1 *= (1.f - s1);
        }
    }
}

// ---------------- kernel: stage-2 spikes from g_H1 ----------------
__global__ void spike2_kernel() {
    int gid = blockIdx.x * 256 + threadIdx.x;       // 0 .. 32*384*128-1
    int w = gid & 127;
    int c = (gid >> 7) % C;
    int p = gid / (C * 128);
    float tau = expert_tau(g_pair_e[p]);
    const float* hb = g_H1 + (((size_t)p * C + c) * HW + 2 * w) * T;
    float4 a0 = *(const float4*)hb;
    float4 a1 = *(const float4*)(hb + 4);
    float* dst = g_SPg + ((size_t)p * C + c) * NCOL + w;
#pragma unroll
    for (int hwi = 0; hwi < 2; hwi++) {
        float4 a = hwi ? a1 : a0;
        float v = 0.f;
#pragma unroll
        for (int t = 0; t < T; t++) {
            float xv = ((const float*)&a)[t];
            v = v + (xv - v) / tau;
            float s = (v >= 1.0f) ? 1.f : 0.f;
            dst[(hwi * 4 + t) * 128] = s;
            v *= (1.f - s);
        }
    }
}

// ---------------- kernel: expert GEMM stage ----------------
// A fragments in g_WT are already alpha-scaled + tf32-rounded -> pure LDS mainloop.
// STAGE 1: z = p (32), K = 384, acc = alpha*g, h1 = x + acc + beta -> g_H1
// STAGE 2: z = b (16), K = 2*384: pair pbase+1 first, rescale acc by pw1/pw0 (<=1),
//          then pair pbase; epilogue out = pw0*(acc + h0 + be0) + pw1*(h1 + be1)
template<int STAGE>
__global__ __launch_bounds__(NTHREADS, 2)
void expert_kernel(const float* __restrict__ x,
                   const float* __restrict__ bg,
                   const float* __restrict__ bnsg,
                   const float* __restrict__ bnbg,
                   float* __restrict__ outp) {
    extern __shared__ float sm[];
    float* Asm = sm;                 // 2 * ACHUNK
    float* Bsm = sm + 2 * ACHUNK;    // 2 * BCHUNK

    const int mb = blockIdx.y;
    const int m0 = mb * BM;
    const int n0 = blockIdx.x * BN;
    const int w0 = blockIdx.x * 16;

    const int tid  = threadIdx.x;
    const int lane = tid & 31;
    const int warp = tid >> 5;
    const int wmid = warp >> 1;
    const int wm   = wmid * 32;
    const int wn   = (warp & 1) * 64;
    const int wn8  = (warp & 1) * 8;
    const int l4   = lane >> 2;

    const int nph   = (STAGE == 1) ? 1 : 2;
    const int pbase = (STAGE == 1) ? blockIdx.z : 2 * blockIdx.z;
    const int b     = (STAGE == 1) ? (pbase >> 1) : blockIdx.z;
    const int eoff  = (STAGE == 1) ? 0 : 8;
    const int KT    = nph * NK;
    const float rinv = rsqrtf(1.0f + 1e-5f);

    int   pe[2];
    float ppw[2];
#pragma unroll
    for (int ph = 0; ph < 2; ph++) {
        if (ph >= nph) break;
        pe[ph]  = g_pair_e[pbase + ph];
        ppw[ph] = g_pair_w[pbase + ph];
    }

    float acc[2][8][4];
#pragma unroll
    for (int mi = 0; mi < 2; mi++)
#pragma unroll
        for (int ni = 0; ni < 8; ni++)
#pragma unroll
            for (int k = 0; k < 4; k++) acc[mi][ni][k] = 0.f;

    auto copy_tiles = [&](int kt, int s) {
        // stage 2 processes the weaker pair (pbase+1) FIRST
        int ph = (STAGE == 2 && kt < NK) ? 1 : 0;
        int kc = (kt >= NK) ? kt - NK : kt;
        const float* Asrc = g_WT + (((size_t)(eoff + pe[ph]) * 3 + mb) * NK + kc) * 4096;
        float* Asd = Asm + s * ACHUNK;
#pragma unroll
        for (int it = 0; it < 4; it++) {
            int idx = tid + it * NTHREADS;     // 0..1023
            int p4 = idx >> 3, sub = idx & 7;
            cp_async16((uint32_t)__cvta_generic_to_shared(
                           Asd + (p4 >> 5) * 1152 + (p4 & 31) * 36 + sub * 4),
                       Asrc + (size_t)p4 * 32 + sub * 4);
        }
        const float* Bsrc = g_SPg + ((size_t)(pbase + ph) * C + kc * 32) * NCOL + w0;
        float* Bsd = Bsm + s * BCHUNK;
#pragma unroll
        for (int it = 0; it < 4; it++) {
            int idx = tid + it * NTHREADS;     // 0..1023
            int cl = idx >> 5, j = (idx >> 2) & 7, sub = idx & 3;
            cp_async16((uint32_t)__cvta_generic_to_shared(
                           Bsd + cl * 132 + j * 16 + sub * 4),
                       Bsrc + ((size_t)cl * 8 + j) * 128 + sub * 4);
        }
    };

    copy_tiles(0, 0);
    asm volatile("cp.async.commit_group;\n" ::);

    for (int kt = 0; kt < KT; kt++) {
        asm volatile("cp.async.wait_group 0;\n" ::);
        __syncthreads();
        if (kt + 1 < KT) copy_tiles(kt + 1, (kt + 1) & 1);
        asm volatile("cp.async.commit_group;\n" ::);

        const int s = kt & 1;
        const uint4* Ab = (const uint4*)(Asm + s * ACHUNK + wmid * 1152 + lane * 36);
        const float* Bb = Bsm + s * BCHUNK + (lane & 3) * 132 + l4 * 16 + wn8;

#pragma unroll
        for (int kki = 0; kki < 4; kki++) {
            uint4 ua0 = Ab[kki * 2];       // mi=0 fragment (pre-scaled tf32)
            uint4 ua1 = Ab[kki * 2 + 1];   // mi=1 fragment

            const float* br0 = Bb + kki * 8 * 132;
            const float* br1 = br0 + 4 * 132;
            float4 b00 = *(const float4*)br0;
            float4 b01 = *(const float4*)(br0 + 4);
            float4 b10 = *(const float4*)br1;
            float4 b11 = *(const float4*)(br1 + 4);
            float bf0a[8] = {b00.x, b00.y, b00.z, b00.w, b01.x, b01.y, b01.z, b01.w};
            float bf1a[8] = {b10.x, b10.y, b10.z, b10.w, b11.x, b11.y, b11.z, b11.w};

#pragma unroll
            for (int ni = 0; ni < 8; ni++) {
                uint32_t bf0 = __float_as_uint(bf0a[ni]);
                uint32_t bf1 = __float_as_uint(bf1a[ni]);
                asm volatile(
                    "mma.sync.aligned.m16n8k8.row.col.f32.tf32.tf32.f32 "
                    "{%0,%1,%2,%3}, {%4,%5,%6,%7}, {%8,%9}, {%0,%1,%2,%3};"
                    : "+f"(acc[0][ni][0]), "+f"(acc[0][ni][1]),
                      "+f"(acc[0][ni][2]), "+f"(acc[0][ni][3])
                    : "r"(ua0.x), "r"(ua0.y), "r"(ua0.z), "r"(ua0.w),
                      "r"(bf0), "r"(bf1));
                asm volatile(
                    "mma.sync.aligned.m16n8k8.row.col.f32.tf32.tf32.f32 "
                    "{%0,%1,%2,%3}, {%4,%5,%6,%7}, {%8,%9}, {%0,%1,%2,%3};"
                    : "+f"(acc[1][ni][0]), "+f"(acc[1][ni][1]),
                      "+f"(acc[1][ni][2]), "+f"(acc[1][ni][3])
                    : "r"(ua1.x), "r"(ua1.y), "r"(ua1.z), "r"(ua1.w),
                      "r"(bf0), "r"(bf1));
            }
        }

        // stage-2 phase switch: acc holds S1; fold in pw1/pw0 (<= 1, overflow-safe)
        if (STAGE == 2 && kt == NK - 1) {
            float f = ppw[1] / ppw[0];
#pragma unroll
            for (int mi = 0; mi < 2; mi++)
#pragma unroll
                for (int ni = 0; ni < 8; ni++)
#pragma unroll
                    for (int k = 0; k < 4; k++) acc[mi][ni][k] *= f;
        }
    }

    // ---- epilogue ----
#pragma unroll
    for (int mi = 0; mi < 2; mi++) {
#pragma unroll
        for (int half = 0; half < 2; half++) {
            int o = m0 + wm + mi * 16 + l4 + half * 8;
            if (STAGE == 1) {
                int e = pe[0];
                float alpha = bnsg[e * C + o] * rinv;
                float beta  = bg[e * C + o] * alpha + bnbg[e * C + o];
#pragma unroll
                for (int ni = 0; ni < 8; ni++) {
                    int n  = n0 + wn + ni * 8 + (lane & 3) * 2;
                    int t  = n & 3;
                    int hw = n >> 2;
                    size_t hidx = (((size_t)pbase * C + o) * HW + hw) * T + t;
                    size_t xi0  = (((size_t)t * BSZ + b) * C + o) * HW + hw;
                    size_t xi1  = (((size_t)(t + 1) * BSZ + b) * C + o) * HW + hw;
                    float g0 = acc[mi][ni][half * 2 + 0] + beta;
                    float g1 = acc[mi][ni][half * 2 + 1] + beta;
                    *(float2*)&g_H1[hidx] = make_float2(x[xi0] + g0, x[xi1] + g1);
                }
            } else {
                float a0 = bnsg[pe[0] * C + o] * rinv;
                float a1 = bnsg[pe[1] * C + o] * rinv;
                float be0 = bg[pe[0] * C + o] * a0 + bnbg[pe[0] * C + o];
                float be1 = bg[pe[1] * C + o] * a1 + bnbg[pe[1] * C + o];
#pragma unroll
                for (int ni = 0; ni < 8; ni++) {
                    int n  = n0 + wn + ni * 8 + (lane & 3) * 2;
                    int t  = n & 3;
                    int hw = n >> 2;
                    size_t h0i = (((size_t)(pbase + 0) * C + o) * HW + hw) * T + t;
                    size_t h1i = (((size_t)(pbase + 1) * C + o) * HW + hw) * T + t;
                    float2 h0 = *(const float2*)&g_H1[h0i];
                    float2 h1 = *(const float2*)&g_H1[h1i];
                    size_t xi0 = (((size_t)t * BSZ + b) * C + o) * HW + hw;
                    size_t xi1 = (((size_t)(t + 1) * BSZ + b) * C + o) * HW + hw;
                    // acc = S0 + (pw1/pw0)*S1  ->  out = pw0*acc + pw0*(h0+be0) + pw1*(h1+be1)
                    outp[xi0] = ppw[0] * (acc[mi][ni][half * 2 + 0] + h0.x + be0)
                              + ppw[1] * (h1.x + be1);
                    outp[xi1] = ppw[0] * (acc[mi][ni][half * 2 + 1] + h0.y + be0)
                              + ppw[1] * (h1.y + be1);
                }
            }
        }
    }
}

// ---------------- launcher ----------------
extern "C" void kernel_launch(void* const* d_in, const int* in_sizes, int n_in,
                              void* d_out, int out_size) {
    const float* x   = (const float*)d_in[0];
    const float* rW  = (const float*)d_in[1];
    const float* rb  = (const float*)d_in[2];
    const float* rbs = (const float*)d_in[3];
    const float* rbb = (const float*)d_in[4];
    const float* W1  = (const float*)d_in[5];
    const float* b1  = (const float*)d_in[6];
    const float* s1  = (const float*)d_in[7];
    const float* bb1 = (const float*)d_in[8];
    const float* W2  = (const float*)d_in[9];
    const float* b2  = (const float*)d_in[10];
    const float* s2  = (const float*)d_in[11];
    const float* bb2 = (const float*)d_in[12];
    float* out = (float*)d_out;

    cudaFuncSetAttribute(expert_kernel<1>, cudaFuncAttributeMaxDynamicSharedMemorySize, SMEM_BYTES);
    cudaFuncSetAttribute(expert_kernel<2>, cudaFuncAttributeMaxDynamicSharedMemorySize, SMEM_BYTES);

    wtrans_kernel<<<288, 256>>>(W1, s1, 0);
    wtrans_kernel<<<288, 256>>>(W2, s2, 8);
    router_s_kernel<<<BSZ * C, 256>>>(x);
    routing_kernel<<<1, 1024>>>(rW, rb, rbs, rbb);

    spike1_kernel<<<(BSZ * C * 128) / 256, 256>>>(x);
    dim3 grid1(NCOL / BN, C / BM, 32);
    expert_kernel<1><<<grid1, NTHREADS, SMEM_BYTES>>>(x, b1, s1, bb1, out);

    spike2_kernel<<<(32 * C * 128) / 256, 256>>>();
    dim3 grid2(NCOL / BN, C / BM, 16);
    expert_kernel<2><<<grid2, NTHREADS, SMEM_BYTES>>>(x, b2, s2, bb2, out);
}

// round 11
// speedup vs baseline: 1.8260x; 1.3432x over previous
#include <cuda_runtime.h>
#include <cuda_fp16.h>
#include <cstdint>

#define T 4
#define BSZ 16
#define C 384
#define HW 256
#define NEXP 8
#define NCOL 1024   // T*HW columns, n = hw*4 + t
#define BM 128
#define BN 128
#define BK 32
#define NK 12       // C / BK
#define NTHREADS 256
#define AWORDS 2560 // A chunk smem words: 4 wmid * 32 lane * 20 (16 data + 4 pad)
#define BWORDS 2112 // B chunk smem words: 16 group * 132 (128 data + 4 pad)
#define SMEM_BYTES ((2 * AWORDS + 2 * BWORDS) * 4)   // 37376

// ---------------- device scratch (no allocations allowed) ----------------
__device__ float    g_S[BSZ * C];
__device__ float    g_logit[BSZ * NEXP];
__device__ int      g_pair_e[BSZ * 2];
__device__ float    g_pair_w[BSZ * 2];
__device__ float    g_H1[(size_t)32 * C * HW * T];      // h1 scratch [p][c][hw][t] fp32
__device__ uint32_t g_SPh[(size_t)32 * NK * 16 * 8 * 128]; // fp16x2 spikes [p][kc][g][l4][w]
__device__ uint4    g_WTh[(size_t)16 * 36 * 512];       // fp16 frag-major alpha-scaled W

// ---------------- helpers ----------------
__device__ __forceinline__ float expert_tau(int e) {
    return 1.5f + (float)e * (2.5f / 7.0f);
}
__device__ __forceinline__ void cp_async16(uint32_t smem_addr, const void* gptr) {
    asm volatile("cp.async.cg.shared.global [%0], [%1], 16;\n" :: "r"(smem_addr), "l"(gptr));
}
__device__ __forceinline__ uint32_t pack_h2(float lo, float hi) {
    uint32_t r;
    asm("cvt.rn.f16x2.f32 %0, %1, %2;" : "=r"(r) : "f"(hi), "f"(lo));
    return r;
}

// ---------------- kernel: W -> fp16 fragment-major, alpha-scaled ----------------
// chunk (e,mb,kc) = 512 uint4: [wmid 4][lane 32][kki 2][mi 2]; uint4 = {a0,a1,a2,a3}
// a0=(m0,k0..k0+1) a1=(m0+8,k0..+1) a2=(m0,k0+8..9) a3=(m0+8,k0+8..9)
__global__ void wtrans_kernel(const float* __restrict__ W, const float* __restrict__ bnsg, int eoff) {
    const int bid = blockIdx.x;            // 288 = e*36 + mb*12 + kc
    const int e  = bid / 36;
    const int mb = (bid / 12) % 3;
    const int kc = bid % 12;
    const float rinv = rsqrtf(1.0f + 1e-5f);
    uint4* dst = g_WTh + (((size_t)(eoff + e) * 3 + mb) * NK + kc) * 512;
#pragma unroll
    for (int it = 0; it < 2; it++) {
        int u = threadIdx.x + it * 256;    // 0..511
        int wmid = u >> 7, lane = (u >> 2) & 31, q4 = u & 3;
        int kki = q4 >> 1, mi = q4 & 1;
        int l4 = lane >> 2, q = lane & 3;
        int m0 = mb * 128 + wmid * 32 + mi * 16 + l4;
        int k0 = kc * 32 + kki * 16 + 2 * q;
        const float* s0 = W + ((size_t)e * C + m0) * C + k0;
        float2 alo = *(const float2*)s0;
        float2 ahi = *(const float2*)(s0 + 8);
        float2 blo = *(const float2*)(s0 + 8 * C);
        float2 bhi = *(const float2*)(s0 + 8 * C + 8);
        float al0 = bnsg[e * C + m0] * rinv;
        float al1 = bnsg[e * C + m0 + 8] * rinv;
        uint4 o;
        o.x = pack_h2(alo.x * al0, alo.y * al0);
        o.y = pack_h2(blo.x * al1, blo.y * al1);
        o.z = pack_h2(ahi.x * al0, ahi.y * al0);
        o.w = pack_h2(bhi.x * al1, bhi.y * al1);
        dst[u] = o;
    }
}

// ---------------- kernel: router S[b,c] ----------------
__global__ void router_s_kernel(const float* __restrict__ x) {
    int bc = blockIdx.x;
    int b = bc / C, c = bc % C;
    int hw = threadIdx.x;
    const float* px = x + (((size_t)b) * C + c) * HW + hw;
    float v = 0.f, cnt = 0.f;
#pragma unroll
    for (int t = 0; t < T; t++) {
        float xv = px[(size_t)t * BSZ * C * HW];
        v = v + (xv - v) / 2.0f;
        float s = (v >= 1.0f) ? 1.f : 0.f;
        cnt += s;
        v = v * (1.f - s);
    }
#pragma unroll
    for (int o = 16; o > 0; o >>= 1) cnt += __shfl_down_sync(0xffffffffu, cnt, o);
    __shared__ float red[8];
    if ((hw & 31) == 0) red[hw >> 5] = cnt;
    __syncthreads();
    if (hw < 8) {
        float vv = red[hw];
#pragma unroll
        for (int o = 4; o > 0; o >>= 1) vv += __shfl_down_sync(0xffu, vv, o);
        if (hw == 0) g_S[bc] = vv;
    }
}

// ---------------- kernel: per-(b,e) logit (128 CTAs, deterministic) ----------------
__global__ void routing_dot(const float* __restrict__ rW, const float* __restrict__ rb,
                            const float* __restrict__ rbs, const float* __restrict__ rbb) {
    int blk = blockIdx.x, b = blk >> 3, e = blk & 7;
    int tid = threadIdx.x;   // 128
    const float* w = rW + e * C;
    const float* s = g_S + b * C;
    float dot = 0.f;
#pragma unroll
    for (int i = 0; i < 3; i++) dot += w[tid + i * 128] * s[tid + i * 128];
#pragma unroll
    for (int o = 16; o > 0; o >>= 1) dot += __shfl_down_sync(0xffffffffu, dot, o);
    __shared__ float red[4];
    if ((tid & 31) == 0) red[tid >> 5] = dot;
    __syncthreads();
    if (tid == 0) {
        float tot = red[0] + red[1] + red[2] + red[3];
        float inv = rbs[e] * rsqrtf(1.0f + 1e-5f);
        g_logit[blk] = (tot * (1.0f / (float)NCOL) + rb[e]) * inv + rbb[e];
    }
}

// ---------------- kernel: top-2 per batch ----------------
__global__ void routing_top2() {
    int b = threadIdx.x;     // 16
    float lg[NEXP];
#pragma unroll
    for (int e = 0; e < NEXP; e++) lg[e] = g_logit[b * 8 + e];
    int i0 = 0; float l0 = lg[0];
#pragma unroll
    for (int e = 1; e < NEXP; e++) if (lg[e] > l0) { l0 = lg[e]; i0 = e; }
    int i1 = -1; float l1 = -3.4e38f;
#pragma unroll
    for (int e = 0; e < NEXP; e++) if (e != i0 && lg[e] > l1) { l1 = lg[e]; i1 = e; }
    float e1 = expf(l1 - l0);
    float denom = 1.0f + e1;
    g_pair_e[2 * b]     = i0;  g_pair_w[2 * b]     = 1.0f / denom;
    g_pair_e[2 * b + 1] = i1;  g_pair_w[2 * b + 1] = e1 / denom;
}

// ---------------- kernel: stage-1 fp16 spikes (both pairs, channel-pair packed) ----------------
// thread = (b, cpair, w): c = 2cp, 2cp+1; hw = 2w, 2w+1; n = 8w + l4, l4 = hwi*4 + t
// writes g_SPh[p][kc][g][l4][w] half2 = (spike(c0), spike(c0+1))
__global__ void spike1_kernel(const float* __restrict__ x) {
    int gid = blockIdx.x * 256 + threadIdx.x;   // 0 .. 16*192*128-1
    int w = gid & 127;
    int cp = (gid >> 7) % 192;
    int b = gid / (192 * 128);
    int c0 = cp * 2;
    float tau0 = expert_tau(g_pair_e[2 * b]);
    float tau1 = expert_tau(g_pair_e[2 * b + 1]);
    float2 inA[T], inB[T];
#pragma unroll
    for (int t = 0; t < T; t++) {
        const float* px = x + (((size_t)t * BSZ + b) * C + c0) * HW + 2 * w;
        inA[t] = *(const float2*)px;
        inB[t] = *(const float2*)(px + HW);
    }
    uint32_t out0[8], out1[8];
#pragma unroll
    for (int hwi = 0; hwi < 2; hwi++) {
        float vA0 = 0.f, vB0 = 0.f, vA1 = 0.f, vB1 = 0.f;
#pragma unroll
        for (int t = 0; t < T; t++) {
            float xa = hwi ? inA[t].y : inA[t].x;
            float xb = hwi ? inB[t].y : inB[t].x;
            vA0 = vA0 + (xa - vA0) / tau0; bool sa0 = vA0 >= 1.f; vA0 = sa0 ? 0.f : vA0;
            vB0 = vB0 + (xb - vB0) / tau0; bool sb0 = vB0 >= 1.f; vB0 = sb0 ? 0.f : vB0;
            vA1 = vA1 + (xa - vA1) / tau1; bool sa1 = vA1 >= 1.f; vA1 = sa1 ? 0.f : vA1;
            vB1 = vB1 + (xb - vB1) / tau1; bool sb1 = vB1 >= 1.f; vB1 = sb1 ? 0.f : vB1;
            out0[hwi * 4 + t] = (sa0 ? 0x3C00u : 0u) | (sb0 ? 0x3C000000u : 0u);
            out1[hwi * 4 + t] = (sa1 ? 0x3C00u : 0u) | (sb1 ? 0x3C000000u : 0u);
        }
    }
    int kc = c0 >> 5;
    int cl = c0 & 31;
    int g = (cl >> 4) * 8 + ((cl >> 3) & 1) * 4 + ((cl >> 1) & 3);
    uint32_t* d0 = g_SPh + (size_t)(((2 * b) * NK + kc) * 16 + g) * (8 * 128) + w;
    uint32_t* d1 = g_SPh + (size_t)(((2 * b + 1) * NK + kc) * 16 + g) * (8 * 128) + w;
#pragma unroll
    for (int l4 = 0; l4 < 8; l4++) { d0[l4 * 128] = out0[l4]; d1[l4 * 128] = out1[l4]; }
}

// ---------------- kernel: stage-2 fp16 spikes from g_H1 ----------------
__global__ void spike2_kernel() {
    int gid = blockIdx.x * 256 + threadIdx.x;   // 0 .. 32*192*128-1
    int w = gid & 127;
    int cp = (gid >> 7) % 192;
    int p = gid / (192 * 128);
    int c0 = cp * 2;
    float tau = expert_tau(g_pair_e[p]);
    const float* hb = g_H1 + (((size_t)p * C + c0) * HW + 2 * w) * T;
    float4 aA0 = *(const float4*)hb;                 // c0,   hw=2w
    float4 aA1 = *(const float4*)(hb + 4);           // c0,   hw=2w+1
    float4 aB0 = *(const float4*)(hb + HW * T);      // c0+1, hw=2w
    float4 aB1 = *(const float4*)(hb + HW * T + 4);  // c0+1, hw=2w+1
    uint32_t out[8];
#pragma unroll
    for (int hwi = 0; hwi < 2; hwi++) {
        float4 a = hwi ? aA1 : aA0;
        float4 bb = hwi ? aB1 : aB0;
        float va = 0.f, vb = 0.f;
#pragma unroll
        for (int t = 0; t < T; t++) {
            float xa = ((const float*)&a)[t];
            float xb = ((const float*)&bb)[t];
            va = va + (xa - va) / tau; bool sa = va >= 1.f; va = sa ? 0.f : va;
            vb = vb + (xb - vb) / tau; bool sb = vb >= 1.f; vb = sb ? 0.f : vb;
            out[hwi * 4 + t] = (sa ? 0x3C00u : 0u) | (sb ? 0x3C000000u : 0u);
        }
    }
    int kc = c0 >> 5;
    int cl = c0 & 31;
    int g = (cl >> 4) * 8 + ((cl >> 3) & 1) * 4 + ((cl >> 1) & 3);
    uint32_t* d0 = g_SPh + (size_t)((p * NK + kc) * 16 + g) * (8 * 128) + w;
#pragma unroll
    for (int l4 = 0; l4 < 8; l4++) d0[l4 * 128] = out[l4];
}

// ---------------- kernel: expert GEMM stage (fp16 m16n8k16) ----------------
template<int STAGE>
__global__ __launch_bounds__(NTHREADS, 2)
void expert_kernel(const float* __restrict__ x,
                   const float* __restrict__ bg,
                   const float* __restrict__ bnsg,
                   const float* __restrict__ bnbg,
                   float* __restrict__ outp) {
    extern __shared__ uint32_t smw[];
    const int mb = blockIdx.y;
    const int m0 = mb * BM;
    const int n0 = blockIdx.x * BN;
    const int w0 = blockIdx.x * 16;

    const int tid  = threadIdx.x;
    const int lane = tid & 31;
    const int warp = tid >> 5;
    const int wmid = warp >> 1;
    const int wm   = wmid * 32;
    const int wn   = (warp & 1) * 64;
    const int wn8  = (warp & 1) * 8;
    const int l4   = lane >> 2;
    const int q    = lane & 3;

    const int nph   = (STAGE == 1) ? 1 : 2;
    const int pbase = (STAGE == 1) ? blockIdx.z : 2 * blockIdx.z;
    const int b     = (STAGE == 1) ? (pbase >> 1) : blockIdx.z;
    const int eoff  = (STAGE == 1) ? 0 : 8;
    const int KT    = nph * NK;
    const float rinv = rsqrtf(1.0f + 1e-5f);

    int   pe[2];
    float ppw[2];
#pragma unroll
    for (int ph = 0; ph < 2; ph++) {
        if (ph >= nph) break;
        pe[ph]  = g_pair_e[pbase + ph];
        ppw[ph] = g_pair_w[pbase + ph];
    }

    float acc[2][8][4];
#pragma unroll
    for (int mi = 0; mi < 2; mi++)
#pragma unroll
        for (int ni = 0; ni < 8; ni++)
#pragma unroll
            for (int k = 0; k < 4; k++) acc[mi][ni][k] = 0.f;

    auto copy_tiles = [&](int kt, int s) {
        int ph = (STAGE == 2 && kt < NK) ? 1 : 0;   // stage 2: weaker pair first
        int kc = (kt >= NK) ? kt - NK : kt;
        const uint4* Asrc = g_WTh + (((size_t)(eoff + pe[ph]) * 3 + mb) * NK + kc) * 512;
        uint32_t* Asd = smw + s * AWORDS;
#pragma unroll
        for (int it = 0; it < 2; it++) {
            int u = tid + it * 256;
            int wmid_ = u >> 7, lane_ = (u >> 2) & 31, q4 = u & 3;
            cp_async16((uint32_t)__cvta_generic_to_shared(
                           Asd + (wmid_ * 32 + lane_) * 20 + q4 * 4),
                       Asrc + u);
        }
        const uint32_t* Bsrc = g_SPh + (size_t)((pbase + ph) * NK + kc) * (16 * 8 * 128);
        uint32_t* Bsd = smw + 2 * AWORDS + s * BWORDS;
#pragma unroll
        for (int it = 0; it < 2; it++) {
            int u = tid + it * 256;
            int g_ = u >> 5, l4_ = (u >> 2) & 7, wq = u & 3;
            cp_async16((uint32_t)__cvta_generic_to_shared(
                           Bsd + g_ * 132 + l4_ * 16 + wq * 4),
                       Bsrc + (size_t)(g_ * 8 + l4_) * 128 + w0 + wq * 4);
        }
    };

    copy_tiles(0, 0);
    asm volatile("cp.async.commit_group;\n" ::);

    for (int kt = 0; kt < KT; kt++) {
        asm volatile("cp.async.wait_group 0;\n" ::);
        __syncthreads();
        if (kt + 1 < KT) copy_tiles(kt + 1, (kt + 1) & 1);
        asm volatile("cp.async.commit_group;\n" ::);

        const int s = kt & 1;
        const uint4* Ab = (const uint4*)(smw + s * AWORDS + (wmid * 32 + lane) * 20);
        const uint32_t* Bbase = smw + 2 * AWORDS + s * BWORDS + q * 132 + l4 * 16 + wn8;

#pragma unroll
        for (int kki = 0; kki < 2; kki++) {
            uint4 ua0 = Ab[kki * 2 + 0];   // mi=0: {a0,a1,a2,a3}
            uint4 ua1 = Ab[kki * 2 + 1];   // mi=1
            const uint32_t* bp0 = Bbase + (kki * 8) * 132;       // k rows 2q, 2q+1
            const uint32_t* bp1 = Bbase + (kki * 8 + 4) * 132;   // k rows 2q+8, 2q+9
            uint4 rA = *(const uint4*)bp0;
            uint4 rB = *(const uint4*)(bp0 + 4);
            uint4 sA = *(const uint4*)bp1;
            uint4 sB = *(const uint4*)(bp1 + 4);
            uint32_t b0[8] = {rA.x, rA.y, rA.z, rA.w, rB.x, rB.y, rB.z, rB.w};
            uint32_t b1[8] = {sA.x, sA.y, sA.z, sA.w, sB.x, sB.y, sB.z, sB.w};
#pragma unroll
            for (int ni = 0; ni < 8; ni++) {
                asm volatile(
                    "mma.sync.aligned.m16n8k16.row.col.f32.f16.f16.f32 "
                    "{%0,%1,%2,%3}, {%4,%5,%6,%7}, {%8,%9}, {%0,%1,%2,%3};"
                    : "+f"(acc[0][ni][0]), "+f"(acc[0][ni][1]),
                      "+f"(acc[0][ni][2]), "+f"(acc[0][ni][3])
                    : "r"(ua0.x), "r"(ua0.y), "r"(ua0.z), "r"(ua0.w),
                      "r"(b0[ni]), "r"(b1[ni]));
                asm volatile(
                    "mma.sync.aligned.m16n8k16.row.col.f32.f16.f16.f32 "
                    "{%0,%1,%2,%3}, {%4,%5,%6,%7}, {%8,%9}, {%0,%1,%2,%3};"
                    : "+f"(acc[1][ni][0]), "+f"(acc[1][ni][1]),
                      "+f"(acc[1][ni][2]), "+f"(acc[1][ni][3])
                    : "r"(ua1.x), "r"(ua1.y), "r"(ua1.z), "r"(ua1.w),
                      "r"(b0[ni]), "r"(b1[ni]));
            }
        }

        // stage-2 phase switch: acc holds weaker pair's sum; fold in pw1/pw0 (<= 1)
        if (STAGE == 2 && kt == NK - 1) {
            float f = ppw[1] / ppw[0];
#pragma unroll
            for (int mi = 0; mi < 2; mi++)
#pragma unroll
                for (int ni = 0; ni < 8; ni++)
#pragma unroll
                    for (int k = 0; k < 4; k++) acc[mi][ni][k] *= f;
        }
    }

    // ---- epilogue ----
#pragma unroll
    for (int mi = 0; mi < 2; mi++) {
#pragma unroll
        for (int half = 0; half < 2; half++) {
            int o = m0 + wm + mi * 16 + l4 + half * 8;
            if (STAGE == 1) {
                int e = pe[0];
                float alpha = bnsg[e * C + o] * rinv;
                float beta  = bg[e * C + o] * alpha + bnbg[e * C + o];
#pragma unroll
                for (int ni = 0; ni < 8; ni++) {
                    int n  = n0 + wn + ni * 8 + (lane & 3) * 2;
                    int t  = n & 3;
                    int hw = n >> 2;
                    size_t hidx = (((size_t)pbase * C + o) * HW + hw) * T + t;
                    size_t xi0  = (((size_t)t * BSZ + b) * C + o) * HW + hw;
                    size_t xi1  = (((size_t)(t + 1) * BSZ + b) * C + o) * HW + hw;
                    float g0 = acc[mi][ni][half * 2 + 0] + beta;
                    float g1 = acc[mi][ni][half * 2 + 1] + beta;
                    *(float2*)&g_H1[hidx] = make_float2(x[xi0] + g0, x[xi1] + g1);
                }
            } else {
                float a0 = bnsg[pe[0] * C + o] * rinv;
                float a1 = bnsg[pe[1] * C + o] * rinv;
                float be0 = bg[pe[0] * C + o] * a0 + bnbg[pe[0] * C + o];
                float be1 = bg[pe[1] * C + o] * a1 + bnbg[pe[1] * C + o];
#pragma unroll
                for (int ni = 0; ni < 8; ni++) {
                    int n  = n0 + wn + ni * 8 + (lane & 3) * 2;
                    int t  = n & 3;
                    int hw = n >> 2;
                    size_t h0i = (((size_t)(pbase + 0) * C + o) * HW + hw) * T + t;
                    size_t h1i = (((size_t)(pbase + 1) * C + o) * HW + hw) * T + t;
                    float2 h0 = *(const float2*)&g_H1[h0i];
                    float2 h1 = *(const float2*)&g_H1[h1i];
                    size_t xi0 = (((size_t)t * BSZ + b) * C + o) * HW + hw;
                    size_t xi1 = (((size_t)(t + 1) * BSZ + b) * C + o) * HW + hw;
                    // acc = S0 + (pw1/pw0)*S1  ->  out = pw0*(acc + h0 + be0) + pw1*(h1 + be1)
                    outp[xi0] = ppw[0] * (acc[mi][ni][half * 2 + 0] + h0.x + be0)
                              + ppw[1] * (h1.x + be1);
                    outp[xi1] = ppw[0] * (acc[mi][ni][half * 2 + 1] + h0.y + be0)
                              + ppw[1] * (h1.y + be1);
                }
            }
        }
    }
}

// ---------------- launcher ----------------
extern "C" void kernel_launch(void* const* d_in, const int* in_sizes, int n_in,
                              void* d_out, int out_size) {
    const float* x   = (const float*)d_in[0];
    const float* rW  = (const float*)d_in[1];
    const float* rb  = (const float*)d_in[2];
    const float* rbs = (const float*)d_in[3];
    const float* rbb = (const float*)d_in[4];
    const float* W1  = (const float*)d_in[5];
    const float* b1  = (const float*)d_in[6];
    const float* s1  = (const float*)d_in[7];
    const float* bb1 = (const float*)d_in[8];
    const float* W2  = (const float*)d_in[9];
    const float* b2  = (const float*)d_in[10];
    const float* s2  = (const float*)d_in[11];
    const float* bb2 = (const float*)d_in[12];
    float* out = (float*)d_out;

    wtrans_kernel<<<288, 256>>>(W1, s1, 0);
    wtrans_kernel<<<288, 256>>>(W2, s2, 8);
    router_s_kernel<<<BSZ * C, 256>>>(x);
    routing_dot<<<128, 128>>>(rW, rb, rbs, rbb);
    routing_top2<<<1, 16>>>();

    spike1_kernel<<<(BSZ * 192 * 128) / 256, 256>>>(x);
    dim3 grid1(NCOL / BN, C / BM, 32);
    expert_kernel<1><<<grid1, NTHREADS, SMEM_BYTES>>>(x, b1, s1, bb1, out);

    spike2_kernel<<<(32 * 192 * 128) / 256, 256>>>();
    dim3 grid2(NCOL / BN, C / BM, 16);
    expert_kernel<2><<<grid2, NTHREADS, SMEM_BYTES>>>(x, b2, s2, bb2, out);
}

// round 15
// speedup vs baseline: 1.8922x; 1.0362x over previous
#include <cuda_runtime.h>
#include <cuda_fp16.h>
#include <cstdint>

#define T 4
#define BSZ 16
#define C 384
#define HW 256
#define NEXP 8
#define NCOL 1024   // T*HW columns, n = hw*4 + t
#define BM 128
#define BN 128
#define NK 12       // C / 32 (sub-chunk granularity of the precomputed layouts)
#define NTHREADS 256
// double-size chunks: 2 sub-chunks of 32 k each per buffered chunk
#define CHUNKA 5120  // words: 2 * (4 wmid * 32 lane * 20)
#define CHUNKB 4224  // words: 2 * (16 group * 132)
#define ABUF (2 * CHUNKA)
#define SMEM_BYTES ((2 * CHUNKA + 2 * CHUNKB) * 4)   // 74752

// ---------------- device scratch (no allocations allowed) ----------------
__device__ float    g_S[BSZ * C];
__device__ float    g_logit[BSZ * NEXP];
__device__ int      g_pair_e[BSZ * 2];
__device__ float    g_pair_w[BSZ * 2];
__device__ float    g_H1[(size_t)32 * C * HW * T];      // h1 scratch [p][c][hw][t] fp32
__device__ uint32_t g_SPh[(size_t)32 * NK * 16 * 8 * 128]; // fp16x2 spikes [p][kc][g][l4][w]
__device__ uint4    g_WTh[(size_t)16 * 36 * 512];       // fp16 frag-major alpha-scaled W

// ---------------- helpers ----------------
__device__ __forceinline__ float expert_tau(int e) {
    return 1.5f + (float)e * (2.5f / 7.0f);
}
__device__ __forceinline__ void cp_async16(uint32_t smem_addr, const void* gptr) {
    asm volatile("cp.async.cg.shared.global [%0], [%1], 16;\n" :: "r"(smem_addr), "l"(gptr));
}
__device__ __forceinline__ uint32_t pack_h2(float lo, float hi) {
    uint32_t r;
    asm("cvt.rn.f16x2.f32 %0, %1, %2;" : "=r"(r) : "f"(hi), "f"(lo));
    return r;
}

// ---------------- kernel: W -> fp16 fragment-major, alpha-scaled ----------------
// chunk (e,mb,kc) = 512 uint4: [wmid 4][lane 32][kki 2][mi 2]; uint4 = {a0,a1,a2,a3}
__global__ void wtrans_kernel(const float* __restrict__ W, const float* __restrict__ bnsg, int eoff) {
    const int bid = blockIdx.x;            // 288 = e*36 + mb*12 + kc
    const int e  = bid / 36;
    const int mb = (bid / 12) % 3;
    const int kc = bid % 12;
    const float rinv = rsqrtf(1.0f + 1e-5f);
    uint4* dst = g_WTh + (((size_t)(eoff + e) * 3 + mb) * NK + kc) * 512;
#pragma unroll
    for (int it = 0; it < 2; it++) {
        int u = threadIdx.x + it * 256;    // 0..511
        int wmid = u >> 7, lane = (u >> 2) & 31, q4 = u & 3;
        int kki = q4 >> 1, mi = q4 & 1;
        int l4 = lane >> 2, q = lane & 3;
        int m0 = mb * 128 + wmid * 32 + mi * 16 + l4;
        int k0 = kc * 32 + kki * 16 + 2 * q;
        const float* s0 = W + ((size_t)e * C + m0) * C + k0;
        float2 alo = *(const float2*)s0;
        float2 ahi = *(const float2*)(s0 + 8);
        float2 blo = *(const float2*)(s0 + 8 * C);
        float2 bhi = *(const float2*)(s0 + 8 * C + 8);
        float al0 = bnsg[e * C + m0] * rinv;
        float al1 = bnsg[e * C + m0 + 8] * rinv;
        uint4 o;
        o.x = pack_h2(alo.x * al0, alo.y * al0);
        o.y = pack_h2(blo.x * al1, blo.y * al1);
        o.z = pack_h2(ahi.x * al0, ahi.y * al0);
        o.w = pack_h2(bhi.x * al1, bhi.y * al1);
        dst[u] = o;
    }
}

// ---------------- kernel: router S[b,c] ----------------
__global__ void router_s_kernel(const float* __restrict__ x) {
    int bc = blockIdx.x;
    int b = bc / C, c = bc % C;
    int hw = threadIdx.x;
    const float* px = x + (((size_t)b) * C + c) * HW + hw;
    float v = 0.f, cnt = 0.f;
#pragma unroll
    for (int t = 0; t < T; t++) {
        float xv = px[(size_t)t * BSZ * C * HW];
        v = v + (xv - v) / 2.0f;
        float s = (v >= 1.0f) ? 1.f : 0.f;
        cnt += s;
        v = v * (1.f - s);
    }
#pragma unroll
    for (int o = 16; o > 0; o >>= 1) cnt += __shfl_down_sync(0xffffffffu, cnt, o);
    __shared__ float red[8];
    if ((hw & 31) == 0) red[hw >> 5] = cnt;
    __syncthreads();
    if (hw < 8) {
        float vv = red[hw];
#pragma unroll
        for (int o = 4; o > 0; o >>= 1) vv += __shfl_down_sync(0xffu, vv, o);
        if (hw == 0) g_S[bc] = vv;
    }
}

// ---------------- kernel: per-(b,e) logit (128 CTAs, deterministic) ----------------
__global__ void routing_dot(const float* __restrict__ rW, const float* __restrict__ rb,
                            const float* __restrict__ rbs, const float* __restrict__ rbb) {
    int blk = blockIdx.x, b = blk >> 3, e = blk & 7;
    int tid = threadIdx.x;   // 128
    const float* w = rW + e * C;
    const float* s = g_S + b * C;
    float dot = 0.f;
#pragma unroll
    for (int i = 0; i < 3; i++) dot += w[tid + i * 128] * s[tid + i * 128];
#pragma unroll
    for (int o = 16; o > 0; o >>= 1) dot += __shfl_down_sync(0xffffffffu, dot, o);
    __shared__ float red[4];
    if ((tid & 31) == 0) red[tid >> 5] = dot;
    __syncthreads();
    if (tid == 0) {
        float tot = red[0] + red[1] + red[2] + red[3];
        float inv = rbs[e] * rsqrtf(1.0f + 1e-5f);
        g_logit[blk] = (tot * (1.0f / (float)NCOL) + rb[e]) * inv + rbb[e];
    }
}

// ---------------- kernel: top-2 per batch ----------------
__global__ void routing_top2() {
    int b = threadIdx.x;     // 16
    float lg[NEXP];
#pragma unroll
    for (int e = 0; e < NEXP; e++) lg[e] = g_logit[b * 8 + e];
    int i0 = 0; float l0 = lg[0];
#pragma unroll
    for (int e = 1; e < NEXP; e++) if (lg[e] > l0) { l0 = lg[e]; i0 = e; }
    int i1 = -1; float l1 = -3.4e38f;
#pragma unroll
    for (int e = 0; e < NEXP; e++) if (e != i0 && lg[e] > l1) { l1 = lg[e]; i1 = e; }
    float e1 = expf(l1 - l0);
    float denom = 1.0f + e1;
    g_pair_e[2 * b]     = i0;  g_pair_w[2 * b]     = 1.0f / denom;
    g_pair_e[2 * b + 1] = i1;  g_pair_w[2 * b + 1] = e1 / denom;
}

// ---------------- kernel: stage-1 fp16 spikes (both pairs, channel-pair packed) ----------------
__global__ void spike1_kernel(const float* __restrict__ x) {
    int gid = blockIdx.x * 256 + threadIdx.x;   // 0 .. 16*192*128-1
    int w = gid & 127;
    int cp = (gid >> 7) % 192;
    int b = gid / (192 * 128);
    int c0 = cp * 2;
    float tau0 = expert_tau(g_pair_e[2 * b]);
    float tau1 = expert_tau(g_pair_e[2 * b + 1]);
    float2 inA[T], inB[T];
#pragma unroll
    for (int t = 0; t < T; t++) {
        const float* px = x + (((size_t)t * BSZ + b) * C + c0) * HW + 2 * w;
        inA[t] = *(const float2*)px;
        inB[t] = *(const float2*)(px + HW);
    }
    uint32_t out0[8], out1[8];
#pragma unroll
    for (int hwi = 0; hwi < 2; hwi++) {
        float vA0 = 0.f, vB0 = 0.f, vA1 = 0.f, vB1 = 0.f;
#pragma unroll
        for (int t = 0; t < T; t++) {
            float xa = hwi ? inA[t].y : inA[t].x;
            float xb = hwi ? inB[t].y : inB[t].x;
            vA0 = vA0 + (xa - vA0) / tau0; bool sa0 = vA0 >= 1.f; vA0 = sa0 ? 0.f : vA0;
            vB0 = vB0 + (xb - vB0) / tau0; bool sb0 = vB0 >= 1.f; vB0 = sb0 ? 0.f : vB0;
            vA1 = vA1 + (xa - vA1) / tau1; bool sa1 = vA1 >= 1.f; vA1 = sa1 ? 0.f : vA1;
            vB1 = vB1 + (xb - vB1) / tau1; bool sb1 = vB1 >= 1.f; vB1 = sb1 ? 0.f : vB1;
            out0[hwi * 4 + t] = (sa0 ? 0x3C00u : 0u) | (sb0 ? 0x3C000000u : 0u);
            out1[hwi * 4 + t] = (sa1 ? 0x3C00u : 0u) | (sb1 ? 0x3C000000u : 0u);
        }
    }
    int kc = c0 >> 5;
    int cl = c0 & 31;
    int g = (cl >> 4) * 8 + ((cl >> 3) & 1) * 4 + ((cl >> 1) & 3);
    uint32_t* d0 = g_SPh + (size_t)(((2 * b) * NK + kc) * 16 + g) * (8 * 128) + w;
    uint32_t* d1 = g_SPh + (size_t)(((2 * b + 1) * NK + kc) * 16 + g) * (8 * 128) + w;
#pragma unroll
    for (int l4 = 0; l4 < 8; l4++) { d0[l4 * 128] = out0[l4]; d1[l4 * 128] = out1[l4]; }
}

// ---------------- kernel: stage-2 fp16 spikes from g_H1 ----------------
__global__ void spike2_kernel() {
    int gid = blockIdx.x * 256 + threadIdx.x;   // 0 .. 32*192*128-1
    int w = gid & 127;
    int cp = (gid >> 7) % 192;
    int p = gid / (192 * 128);
    int c0 = cp * 2;
    float tau = expert_tau(g_pair_e[p]);
    const float* hb = g_H1 + (((size_t)p * C + c0) * HW + 2 * w) * T;
    float4 aA0 = *(const float4*)hb;
    float4 aA1 = *(const float4*)(hb + 4);
    float4 aB0 = *(const float4*)(hb + HW * T);
    float4 aB1 = *(const float4*)(hb + HW * T + 4);
    uint32_t out[8];
#pragma unroll
    for (int hwi = 0; hwi < 2; hwi++) {
        float4 a = hwi ? aA1 : aA0;
        float4 bb = hwi ? aB1 : aB0;
        float va = 0.f, vb = 0.f;
#pragma unroll
        for (int t = 0; t < T; t++) {
            float xa = ((const float*)&a)[t];
            float xb = ((const float*)&bb)[t];
            va = va + (xa - va) / tau; bool sa = va >= 1.f; va = sa ? 0.f : va;
            vb = vb + (xb - vb) / tau; bool sb = vb >= 1.f; vb = sb ? 0.f : vb;
            out[hwi * 4 + t] = (sa ? 0x3C00u : 0u) | (sb ? 0x3C000000u : 0u);
        }
    }
    int kc = c0 >> 5;
    int cl = c0 & 31;
    int g = (cl >> 4) * 8 + ((cl >> 3) & 1) * 4 + ((cl >> 1) & 3);
    uint32_t* d0 = g_SPh + (size_t)((p * NK + kc) * 16 + g) * (8 * 128) + w;
#pragma unroll
    for (int l4 = 0; l4 < 8; l4++) d0[l4 * 128] = out[l4];
}

// ---------------- kernel: expert GEMM stage (fp16 m16n8k16, BK=64 chunks) ----------------
// Each buffered chunk = 2 consecutive 32-k sub-chunks of the precomputed layouts.
// STAGE 1: KT=6, acc = alpha*g;  STAGE 2: KT=12, weaker pair first (kt<6), rescale, then pair 0.
template<int STAGE>
__global__ __launch_bounds__(NTHREADS, 2)
void expert_kernel(const float* __restrict__ x,
                   const float* __restrict__ bg,
                   const float* __restrict__ bnsg,
                   const float* __restrict__ bnbg,
                   float* __restrict__ outp) {
    extern __shared__ uint32_t smw[];
    const int mb = blockIdx.y;
    const int m0 = mb * BM;
    const int n0 = blockIdx.x * BN;
    const int w0 = blockIdx.x * 16;

    const int tid  = threadIdx.x;
    const int lane = tid & 31;
    const int warp = tid >> 5;
    const int wmid = warp >> 1;
    const int wm   = wmid * 32;
    const int wn   = (warp & 1) * 64;
    const int wn8  = (warp & 1) * 8;
    const int l4   = lane >> 2;
    const int q    = lane & 3;

    const int pbase = (STAGE == 1) ? blockIdx.z : 2 * blockIdx.z;
    const int b     = (STAGE == 1) ? (pbase >> 1) : blockIdx.z;
    const int eoff  = (STAGE == 1) ? 0 : 8;
    const int KT    = (STAGE == 1) ? 6 : 12;   // BK=64 chunks
    const float rinv = rsqrtf(1.0f + 1e-5f);

    int   pe[2];
    float ppw[2];
    pe[0] = g_pair_e[pbase];  ppw[0] = g_pair_w[pbase];
    pe[1] = (STAGE == 2) ? g_pair_e[pbase + 1] : 0;
    ppw[1] = (STAGE == 2) ? g_pair_w[pbase + 1] : 0.f;

    float acc[2][8][4];
#pragma unroll
    for (int mi = 0; mi < 2; mi++)
#pragma unroll
        for (int ni = 0; ni < 8; ni++)
#pragma unroll
            for (int k = 0; k < 4; k++) acc[mi][ni][k] = 0.f;

    auto copy_tiles = [&](int kt, int s) {
        int ph = (STAGE == 2 && kt < 6) ? 1 : 0;   // stage 2: weaker pair first
        int kc0 = ((kt >= 6) ? kt - 6 : kt) * 2;   // first 32-k sub-chunk index
#pragma unroll
        for (int h = 0; h < 2; h++) {
            int kc = kc0 + h;
            const uint4* Asrc = g_WTh + (((size_t)(eoff + pe[ph]) * 3 + mb) * NK + kc) * 512;
            uint32_t* Asd = smw + s * CHUNKA + h * 2560;
#pragma unroll
            for (int it = 0; it < 2; it++) {
                int u = tid + it * 256;
                int wmid_ = u >> 7, lane_ = (u >> 2) & 31, q4 = u & 3;
                cp_async16((uint32_t)__cvta_generic_to_shared(
                               Asd + (wmid_ * 32 + lane_) * 20 + q4 * 4),
                           Asrc + u);
            }
            const uint32_t* Bsrc = g_SPh + (size_t)((pbase + ph) * NK + kc) * (16 * 8 * 128);
            uint32_t* Bsd = smw + ABUF + s * CHUNKB + h * 2112;
#pragma unroll
            for (int it = 0; it < 2; it++) {
                int u = tid + it * 256;
                int g_ = u >> 5, l4_ = (u >> 2) & 7, wq = u & 3;
                cp_async16((uint32_t)__cvta_generic_to_shared(
                               Bsd + g_ * 132 + l4_ * 16 + wq * 4),
                           Bsrc + (size_t)(g_ * 8 + l4_) * 128 + w0 + wq * 4);
            }
        }
    };

    copy_tiles(0, 0);
    asm volatile("cp.async.commit_group;\n" ::);

    for (int kt = 0; kt < KT; kt++) {
        asm volatile("cp.async.wait_group 0;\n" ::);
        __syncthreads();
        if (kt + 1 < KT) copy_tiles(kt + 1, (kt + 1) & 1);
        asm volatile("cp.async.commit_group;\n" ::);

        const int s = kt & 1;
#pragma unroll
        for (int h = 0; h < 2; h++) {
            const uint4* Ab = (const uint4*)(smw + s * CHUNKA + h * 2560 + (wmid * 32 + lane) * 20);
            const uint32_t* Bbase = smw + ABUF + s * CHUNKB + h * 2112 + q * 132 + l4 * 16 + wn8;
#pragma unroll
            for (int kki = 0; kki < 2; kki++) {
                uint4 ua0 = Ab[kki * 2 + 0];   // mi=0
                uint4 ua1 = Ab[kki * 2 + 1];   // mi=1
                const uint32_t* bp0 = Bbase + (kki * 8) * 132;
                const uint32_t* bp1 = Bbase + (kki * 8 + 4) * 132;
                uint4 rA = *(const uint4*)bp0;
                uint4 rB = *(const uint4*)(bp0 + 4);
                uint4 sA = *(const uint4*)bp1;
                uint4 sB = *(const uint4*)(bp1 + 4);
                uint32_t b0[8] = {rA.x, rA.y, rA.z, rA.w, rB.x, rB.y, rB.z, rB.w};
                uint32_t b1[8] = {sA.x, sA.y, sA.z, sA.w, sB.x, sB.y, sB.z, sB.w};
#pragma unroll
                for (int ni = 0; ni < 8; ni++) {
                    asm volatile(
                        "mma.sync.aligned.m16n8k16.row.col.f32.f16.f16.f32 "
                        "{%0,%1,%2,%3}, {%4,%5,%6,%7}, {%8,%9}, {%0,%1,%2,%3};"
                        : "+f"(acc[0][ni][0]), "+f"(acc[0][ni][1]),
                          "+f"(acc[0][ni][2]), "+f"(acc[0][ni][3])
                        : "r"(ua0.x), "r"(ua0.y), "r"(ua0.z), "r"(ua0.w),
                          "r"(b0[ni]), "r"(b1[ni]));
                    asm volatile(
                        "mma.sync.aligned.m16n8k16.row.col.f32.f16.f16.f32 "
                        "{%0,%1,%2,%3}, {%4,%5,%6,%7}, {%8,%9}, {%0,%1,%2,%3};"
                        : "+f"(acc[1][ni][0]), "+f"(acc[1][ni][1]),
                          "+f"(acc[1][ni][2]), "+f"(acc[1][ni][3])
                        : "r"(ua1.x), "r"(ua1.y), "r"(ua1.z), "r"(ua1.w),
                          "r"(b0[ni]), "r"(b1[ni]));
                }
            }
        }

        // stage-2 phase switch: after weaker pair (kt==5), fold in pw1/pw0 (<= 1)
        if (STAGE == 2 && kt == 5) {
            float f = ppw[1] / ppw[0];
#pragma unroll
            for (int mi = 0; mi < 2; mi++)
#pragma unroll
                for (int ni = 0; ni < 8; ni++)
#pragma unroll
                    for (int k = 0; k < 4; k++) acc[mi][ni][k] *= f;
        }
    }

    // ---- epilogue ----
#pragma unroll
    for (int mi = 0; mi < 2; mi++) {
#pragma unroll
        for (int half = 0; half < 2; half++) {
            int o = m0 + wm + mi * 16 + l4 + half * 8;
            if (STAGE == 1) {
                int e = pe[0];
                float alpha = bnsg[e * C + o] * rinv;
                float beta  = bg[e * C + o] * alpha + bnbg[e * C + o];
#pragma unroll
                for (int ni = 0; ni < 8; ni++) {
                    int n  = n0 + wn + ni * 8 + (lane & 3) * 2;
                    int t  = n & 3;
                    int hw = n >> 2;
                    size_t hidx = (((size_t)pbase * C + o) * HW + hw) * T + t;
                    size_t xi0  = (((size_t)t * BSZ + b) * C + o) * HW + hw;
                    size_t xi1  = (((size_t)(t + 1) * BSZ + b) * C + o) * HW + hw;
                    float g0 = acc[mi][ni][half * 2 + 0] + beta;
                    float g1 = acc[mi][ni][half * 2 + 1] + beta;
                    *(float2*)&g_H1[hidx] = make_float2(x[xi0] + g0, x[xi1] + g1);
                }
            } else {
                float a0 = bnsg[pe[0] * C + o] * rinv;
                float a1 = bnsg[pe[1] * C + o] * rinv;
                float be0 = bg[pe[0] * C + o] * a0 + bnbg[pe[0] * C + o];
                float be1 = bg[pe[1] * C + o] * a1 + bnbg[pe[1] * C + o];
#pragma unroll
                for (int ni = 0; ni < 8; ni++) {
                    int n  = n0 + wn + ni * 8 + (lane & 3) * 2;
                    int t  = n & 3;
                    int hw = n >> 2;
                    size_t h0i = (((size_t)(pbase + 0) * C + o) * HW + hw) * T + t;
                    size_t h1i = (((size_t)(pbase + 1) * C + o) * HW + hw) * T + t;
                    float2 h0 = *(const float2*)&g_H1[h0i];
                    float2 h1 = *(const float2*)&g_H1[h1i];
                    size_t xi0 = (((size_t)t * BSZ + b) * C + o) * HW + hw;
                    size_t xi1 = (((size_t)(t + 1) * BSZ + b) * C + o) * HW + hw;
                    // acc = S0 + (pw1/pw0)*S1 -> out = pw0*(acc + h0 + be0) + pw1*(h1 + be1)
                    outp[xi0] = ppw[0] * (acc[mi][ni][half * 2 + 0] + h0.x + be0)
                              + ppw[1] * (h1.x + be1);
                    outp[xi1] = ppw[0] * (acc[mi][ni][half * 2 + 1] + h0.y + be0)
                              + ppw[1] * (h1.y + be1);
                }
            }
        }
    }
}

// ---------------- launcher ----------------
extern "C" void kernel_launch(void* const* d_in, const int* in_sizes, int n_in,
                              void* d_out, int out_size) {
    const float* x   = (const float*)d_in[0];
    const float* rW  = (const float*)d_in[1];
    const float* rb  = (const float*)d_in[2];
    const float* rbs = (const float*)d_in[3];
    const float* rbb = (const float*)d_in[4];
    const float* W1  = (const float*)d_in[5];
    const float* b1  = (const float*)d_in[6];
    const float* s1  = (const float*)d_in[7];
    const float* bb1 = (const float*)d_in[8];
    const float* W2  = (const float*)d_in[9];
    const float* b2  = (const float*)d_in[10];
    const float* s2  = (const float*)d_in[11];
    const float* bb2 = (const float*)d_in[12];
    float* out = (float*)d_out;

    cudaFuncSetAttribute(expert_kernel<1>, cudaFuncAttributeMaxDynamicSharedMemorySize, SMEM_BYTES);
    cudaFuncSetAttribute(expert_kernel<2>, cudaFuncAttributeMaxDynamicSharedMemorySize, SMEM_BYTES);

    wtrans_kernel<<<288, 256>>>(W1, s1, 0);
    wtrans_kernel<<<288, 256>>>(W2, s2, 8);
    router_s_kernel<<<BSZ * C, 256>>>(x);
    routing_dot<<<128, 128>>>(rW, rb, rbs, rbb);
    routing_top2<<<1, 16>>>();

    spike1_kernel<<<(BSZ * 192 * 128) / 256, 256>>>(x);
    dim3 grid1(NCOL / BN, C / BM, 32);
    expert_kernel<1><<<grid1, NTHREADS, SMEM_BYTES>>>(x, b1, s1, bb1, out);

    spike2_kernel<<<(32 * 192 * 128) / 256, 256>>>();
    dim3 grid2(NCOL / BN, C / BM, 16);
    expert_kernel<2><<<grid2, NTHREADS, SMEM_BYTES>>>(x, b2, s2, bb2, out);
}

// round 16
// speedup vs baseline: 1.9812x; 1.0470x over previous
#include <cuda_runtime.h>
#include <cuda_fp16.h>
#include <cstdint>

#define T 4
#define BSZ 16
#define C 384
#define HW 256
#define NEXP 8
#define NCOL 1024   // T*HW columns, n = hw*4 + t
#define BM 128
#define BN 128
#define NK 12       // C / 32 (sub-chunk granularity of the precomputed layouts)
#define NTHREADS 256
// double-size chunks: 2 sub-chunks of 32 k each per buffered chunk
#define CHUNKA 5120  // words: 2 * (4 wmid * 32 lane * 20)
#define CHUNKB 4224  // words: 2 * (16 group * 132)
#define ABUF (2 * CHUNKA)
#define SMEM_BYTES ((2 * CHUNKA + 2 * CHUNKB) * 4)   // 74752 (>= 128*132*4 transpose tile)

// ---------------- device scratch (no allocations allowed) ----------------
__device__ float    g_S[BSZ * C];
__device__ float    g_logit[BSZ * NEXP];
__device__ int      g_pair_e[BSZ * 2];
__device__ float    g_pair_w[BSZ * 2];
__device__ float    g_H1[(size_t)32 * C * HW * T];      // h1 scratch [p][c][hw][t] fp32
__device__ uint32_t g_SPh[(size_t)32 * NK * 16 * 8 * 128]; // fp16x2 spikes [p][kc][g][l4][w]
__device__ uint4    g_WTh[(size_t)16 * 36 * 512];       // fp16 frag-major alpha-scaled W

// ---------------- helpers ----------------
__device__ __forceinline__ float expert_tau(int e) {
    return 1.5f + (float)e * (2.5f / 7.0f);
}
__device__ __forceinline__ void cp_async16(uint32_t smem_addr, const void* gptr) {
    asm volatile("cp.async.cg.shared.global [%0], [%1], 16;\n" :: "r"(smem_addr), "l"(gptr));
}
__device__ __forceinline__ uint32_t pack_h2(float lo, float hi) {
    uint32_t r;
    asm("cvt.rn.f16x2.f32 %0, %1, %2;" : "=r"(r) : "f"(hi), "f"(lo));
    return r;
}

// ---------------- kernel: W -> fp16 fragment-major, alpha-scaled ----------------
__global__ void wtrans_kernel(const float* __restrict__ W, const float* __restrict__ bnsg, int eoff) {
    const int bid = blockIdx.x;            // 288 = e*36 + mb*12 + kc
    const int e  = bid / 36;
    const int mb = (bid / 12) % 3;
    const int kc = bid % 12;
    const float rinv = rsqrtf(1.0f + 1e-5f);
    uint4* dst = g_WTh + (((size_t)(eoff + e) * 3 + mb) * NK + kc) * 512;
#pragma unroll
    for (int it = 0; it < 2; it++) {
        int u = threadIdx.x + it * 256;    // 0..511
        int wmid = u >> 7, lane = (u >> 2) & 31, q4 = u & 3;
        int kki = q4 >> 1, mi = q4 & 1;
        int l4 = lane >> 2, q = lane & 3;
        int m0 = mb * 128 + wmid * 32 + mi * 16 + l4;
        int k0 = kc * 32 + kki * 16 + 2 * q;
        const float* s0 = W + ((size_t)e * C + m0) * C + k0;
        float2 alo = *(const float2*)s0;
        float2 ahi = *(const float2*)(s0 + 8);
        float2 blo = *(const float2*)(s0 + 8 * C);
        float2 bhi = *(const float2*)(s0 + 8 * C + 8);
        float al0 = bnsg[e * C + m0] * rinv;
        float al1 = bnsg[e * C + m0 + 8] * rinv;
        uint4 o;
        o.x = pack_h2(alo.x * al0, alo.y * al0);
        o.y = pack_h2(blo.x * al1, blo.y * al1);
        o.z = pack_h2(ahi.x * al0, ahi.y * al0);
        o.w = pack_h2(bhi.x * al1, bhi.y * al1);
        dst[u] = o;
    }
}

// ---------------- kernel: router S[b,c] ----------------
__global__ void router_s_kernel(const float* __restrict__ x) {
    int bc = blockIdx.x;
    int b = bc / C, c = bc % C;
    int hw = threadIdx.x;
    const float* px = x + (((size_t)b) * C + c) * HW + hw;
    float v = 0.f, cnt = 0.f;
#pragma unroll
    for (int t = 0; t < T; t++) {
        float xv = px[(size_t)t * BSZ * C * HW];
        v = v + (xv - v) / 2.0f;
        float s = (v >= 1.0f) ? 1.f : 0.f;
        cnt += s;
        v = v * (1.f - s);
    }
#pragma unroll
    for (int o = 16; o > 0; o >>= 1) cnt += __shfl_down_sync(0xffffffffu, cnt, o);
    __shared__ float red[8];
    if ((hw & 31) == 0) red[hw >> 5] = cnt;
    __syncthreads();
    if (hw < 8) {
        float vv = red[hw];
#pragma unroll
        for (int o = 4; o > 0; o >>= 1) vv += __shfl_down_sync(0xffu, vv, o);
        if (hw == 0) g_S[bc] = vv;
    }
}

// ---------------- kernel: per-(b,e) logit ----------------
__global__ void routing_dot(const float* __restrict__ rW, const float* __restrict__ rb,
                            const float* __restrict__ rbs, const float* __restrict__ rbb) {
    int blk = blockIdx.x, b = blk >> 3, e = blk & 7;
    int tid = threadIdx.x;   // 128
    const float* w = rW + e * C;
    const float* s = g_S + b * C;
    float dot = 0.f;
#pragma unroll
    for (int i = 0; i < 3; i++) dot += w[tid + i * 128] * s[tid + i * 128];
#pragma unroll
    for (int o = 16; o > 0; o >>= 1) dot += __shfl_down_sync(0xffffffffu, dot, o);
    __shared__ float red[4];
    if ((tid & 31) == 0) red[tid >> 5] = dot;
    __syncthreads();
    if (tid == 0) {
        float tot = red[0] + red[1] + red[2] + red[3];
        float inv = rbs[e] * rsqrtf(1.0f + 1e-5f);
        g_logit[blk] = (tot * (1.0f / (float)NCOL) + rb[e]) * inv + rbb[e];
    }
}

// ---------------- kernel: top-2 per batch ----------------
__global__ void routing_top2() {
    int b = threadIdx.x;     // 16
    float lg[NEXP];
#pragma unroll
    for (int e = 0; e < NEXP; e++) lg[e] = g_logit[b * 8 + e];
    int i0 = 0; float l0 = lg[0];
#pragma unroll
    for (int e = 1; e < NEXP; e++) if (lg[e] > l0) { l0 = lg[e]; i0 = e; }
    int i1 = -1; float l1 = -3.4e38f;
#pragma unroll
    for (int e = 0; e < NEXP; e++) if (e != i0 && lg[e] > l1) { l1 = lg[e]; i1 = e; }
    float e1 = expf(l1 - l0);
    float denom = 1.0f + e1;
    g_pair_e[2 * b]     = i0;  g_pair_w[2 * b]     = 1.0f / denom;
    g_pair_e[2 * b + 1] = i1;  g_pair_w[2 * b + 1] = e1 / denom;
}

// ---------------- kernel: stage-1 fp16 spikes ----------------
__global__ void spike1_kernel(const float* __restrict__ x) {
    int gid = blockIdx.x * 256 + threadIdx.x;   // 0 .. 16*192*128-1
    int w = gid & 127;
    int cp = (gid >> 7) % 192;
    int b = gid / (192 * 128);
    int c0 = cp * 2;
    float tau0 = expert_tau(g_pair_e[2 * b]);
    float tau1 = expert_tau(g_pair_e[2 * b + 1]);
    float2 inA[T], inB[T];
#pragma unroll
    for (int t = 0; t < T; t++) {
        const float* px = x + (((size_t)t * BSZ + b) * C + c0) * HW + 2 * w;
        inA[t] = *(const float2*)px;
        inB[t] = *(const float2*)(px + HW);
    }
    uint32_t out0[8], out1[8];
#pragma unroll
    for (int hwi = 0; hwi < 2; hwi++) {
        float vA0 = 0.f, vB0 = 0.f, vA1 = 0.f, vB1 = 0.f;
#pragma unroll
        for (int t = 0; t < T; t++) {
            float xa = hwi ? inA[t].y : inA[t].x;
            float xb = hwi ? inB[t].y : inB[t].x;
            vA0 = vA0 + (xa - vA0) / tau0; bool sa0 = vA0 >= 1.f; vA0 = sa0 ? 0.f : vA0;
            vB0 = vB0 + (xb - vB0) / tau0; bool sb0 = vB0 >= 1.f; vB0 = sb0 ? 0.f : vB0;
            vA1 = vA1 + (xa - vA1) / tau1; bool sa1 = vA1 >= 1.f; vA1 = sa1 ? 0.f : vA1;
            vB1 = vB1 + (xb - vB1) / tau1; bool sb1 = vB1 >= 1.f; vB1 = sb1 ? 0.f : vB1;
            out0[hwi * 4 + t] = (sa0 ? 0x3C00u : 0u) | (sb0 ? 0x3C000000u : 0u);
            out1[hwi * 4 + t] = (sa1 ? 0x3C00u : 0u) | (sb1 ? 0x3C000000u : 0u);
        }
    }
    int kc = c0 >> 5;
    int cl = c0 & 31;
    int g = (cl >> 4) * 8 + ((cl >> 3) & 1) * 4 + ((cl >> 1) & 3);
    uint32_t* d0 = g_SPh + (size_t)(((2 * b) * NK + kc) * 16 + g) * (8 * 128) + w;
    uint32_t* d1 = g_SPh + (size_t)(((2 * b + 1) * NK + kc) * 16 + g) * (8 * 128) + w;
#pragma unroll
    for (int l4 = 0; l4 < 8; l4++) { d0[l4 * 128] = out0[l4]; d1[l4 * 128] = out1[l4]; }
}

// ---------------- kernel: stage-2 fp16 spikes from g_H1 ----------------
__global__ void spike2_kernel() {
    int gid = blockIdx.x * 256 + threadIdx.x;   // 0 .. 32*192*128-1
    int w = gid & 127;
    int cp = (gid >> 7) % 192;
    int p = gid / (192 * 128);
    int c0 = cp * 2;
    float tau = expert_tau(g_pair_e[p]);
    const float* hb = g_H1 + (((size_t)p * C + c0) * HW + 2 * w) * T;
    float4 aA0 = *(const float4*)hb;
    float4 aA1 = *(const float4*)(hb + 4);
    float4 aB0 = *(const float4*)(hb + HW * T);
    float4 aB1 = *(const float4*)(hb + HW * T + 4);
    uint32_t out[8];
#pragma unroll
    for (int hwi = 0; hwi < 2; hwi++) {
        float4 a = hwi ? aA1 : aA0;
        float4 bb = hwi ? aB1 : aB0;
        float va = 0.f, vb = 0.f;
#pragma unroll
        for (int t = 0; t < T; t++) {
            float xa = ((const float*)&a)[t];
            float xb = ((const float*)&bb)[t];
            va = va + (xa - va) / tau; bool sa = va >= 1.f; va = sa ? 0.f : va;
            vb = vb + (xb - vb) / tau; bool sb = vb >= 1.f; vb = sb ? 0.f : vb;
            out[hwi * 4 + t] = (sa ? 0x3C00u : 0u) | (sb ? 0x3C000000u : 0u);
        }
    }
    int kc = c0 >> 5;
    int cl = c0 & 31;
    int g = (cl >> 4) * 8 + ((cl >> 3) & 1) * 4 + ((cl >> 1) & 3);
    uint32_t* d0 = g_SPh + (size_t)((p * NK + kc) * 16 + g) * (8 * 128) + w;
#pragma unroll
    for (int l4 = 0; l4 < 8; l4++) d0[l4 * 128] = out[l4];
}

// ---------------- kernel: expert GEMM stage (fp16 m16n8k16, BK=64 chunks) ----------------
// Mainloop identical to R15. Epilogue: smem transpose -> each thread owns one
// output channel o and 64 consecutive n (16 hw x 4 t) -> fully coalesced IO.
template<int STAGE>
__global__ __launch_bounds__(NTHREADS, 2)
void expert_kernel(const float* __restrict__ x,
                   const float* __restrict__ bg,
                   const float* __restrict__ bnsg,
                   const float* __restrict__ bnbg,
                   float* __restrict__ outp) {
    extern __shared__ uint32_t smw[];
    const int mb = blockIdx.y;
    const int m0 = mb * BM;
    const int n0 = blockIdx.x * BN;
    const int w0 = blockIdx.x * 16;

    const int tid  = threadIdx.x;
    const int lane = tid & 31;
    const int warp = tid >> 5;
    const int wmid = warp >> 1;
    const int wm   = wmid * 32;
    const int wn   = (warp & 1) * 64;
    const int wn8  = (warp & 1) * 8;
    const int l4   = lane >> 2;
    const int q    = lane & 3;

    const int pbase = (STAGE == 1) ? blockIdx.z : 2 * blockIdx.z;
    const int b     = (STAGE == 1) ? (pbase >> 1) : blockIdx.z;
    const int eoff  = (STAGE == 1) ? 0 : 8;
    const int KT    = (STAGE == 1) ? 6 : 12;   // BK=64 chunks
    const float rinv = rsqrtf(1.0f + 1e-5f);

    int   pe[2];
    float ppw[2];
    pe[0] = g_pair_e[pbase];  ppw[0] = g_pair_w[pbase];
    pe[1] = (STAGE == 2) ? g_pair_e[pbase + 1] : 0;
    ppw[1] = (STAGE == 2) ? g_pair_w[pbase + 1] : 0.f;

    float acc[2][8][4];
#pragma unroll
    for (int mi = 0; mi < 2; mi++)
#pragma unroll
        for (int ni = 0; ni < 8; ni++)
#pragma unroll
            for (int k = 0; k < 4; k++) acc[mi][ni][k] = 0.f;

    auto copy_tiles = [&](int kt, int s) {
        int ph = (STAGE == 2 && kt < 6) ? 1 : 0;   // stage 2: weaker pair first
        int kc0 = ((kt >= 6) ? kt - 6 : kt) * 2;
#pragma unroll
        for (int h = 0; h < 2; h++) {
            int kc = kc0 + h;
            const uint4* Asrc = g_WTh + (((size_t)(eoff + pe[ph]) * 3 + mb) * NK + kc) * 512;
            uint32_t* Asd = smw + s * CHUNKA + h * 2560;
#pragma unroll
            for (int it = 0; it < 2; it++) {
                int u = tid + it * 256;
                int wmid_ = u >> 7, lane_ = (u >> 2) & 31, q4 = u & 3;
                cp_async16((uint32_t)__cvta_generic_to_shared(
                               Asd + (wmid_ * 32 + lane_) * 20 + q4 * 4),
                           Asrc + u);
            }
            const uint32_t* Bsrc = g_SPh + (size_t)((pbase + ph) * NK + kc) * (16 * 8 * 128);
            uint32_t* Bsd = smw + ABUF + s * CHUNKB + h * 2112;
#pragma unroll
            for (int it = 0; it < 2; it++) {
                int u = tid + it * 256;
                int g_ = u >> 5, l4_ = (u >> 2) & 7, wq = u & 3;
                cp_async16((uint32_t)__cvta_generic_to_shared(
                               Bsd + g_ * 132 + l4_ * 16 + wq * 4),
                           Bsrc + (size_t)(g_ * 8 + l4_) * 128 + w0 + wq * 4);
            }
        }
    };

    copy_tiles(0, 0);
    asm volatile("cp.async.commit_group;\n" ::);

    for (int kt = 0; kt < KT; kt++) {
        asm volatile("cp.async.wait_group 0;\n" ::);
        __syncthreads();
        if (kt + 1 < KT) copy_tiles(kt + 1, (kt + 1) & 1);
        asm volatile("cp.async.commit_group;\n" ::);

        const int s = kt & 1;
#pragma unroll
        for (int h = 0; h < 2; h++) {
            const uint4* Ab = (const uint4*)(smw + s * CHUNKA + h * 2560 + (wmid * 32 + lane) * 20);
            const uint32_t* Bbase = smw + ABUF + s * CHUNKB + h * 2112 + q * 132 + l4 * 16 + wn8;
#pragma unroll
            for (int kki = 0; kki < 2; kki++) {
                uint4 ua0 = Ab[kki * 2 + 0];   // mi=0
                uint4 ua1 = Ab[kki * 2 + 1];   // mi=1
                const uint32_t* bp0 = Bbase + (kki * 8) * 132;
                const uint32_t* bp1 = Bbase + (kki * 8 + 4) * 132;
                uint4 rA = *(const uint4*)bp0;
                uint4 rB = *(const uint4*)(bp0 + 4);
                uint4 sA = *(const uint4*)bp1;
                uint4 sB = *(const uint4*)(bp1 + 4);
                uint32_t b0[8] = {rA.x, rA.y, rA.z, rA.w, rB.x, rB.y, rB.z, rB.w};
                uint32_t b1[8] = {sA.x, sA.y, sA.z, sA.w, sB.x, sB.y, sB.z, sB.w};
#pragma unroll
                for (int ni = 0; ni < 8; ni++) {
                    asm volatile(
                        "mma.sync.aligned.m16n8k16.row.col.f32.f16.f16.f32 "
                        "{%0,%1,%2,%3}, {%4,%5,%6,%7}, {%8,%9}, {%0,%1,%2,%3};"
                        : "+f"(acc[0][ni][0]), "+f"(acc[0][ni][1]),
                          "+f"(acc[0][ni][2]), "+f"(acc[0][ni][3])
                        : "r"(ua0.x), "r"(ua0.y), "r"(ua0.z), "r"(ua0.w),
                          "r"(b0[ni]), "r"(b1[ni]));
                    asm volatile(
                        "mma.sync.aligned.m16n8k16.row.col.f32.f16.f16.f32 "
                        "{%0,%1,%2,%3}, {%4,%5,%6,%7}, {%8,%9}, {%0,%1,%2,%3};"
                        : "+f"(acc[1][ni][0]), "+f"(acc[1][ni][1]),
                          "+f"(acc[1][ni][2]), "+f"(acc[1][ni][3])
                        : "r"(ua1.x), "r"(ua1.y), "r"(ua1.z), "r"(ua1.w),
                          "r"(b0[ni]), "r"(b1[ni]));
                }
            }
        }

        if (STAGE == 2 && kt == 5) {
            float f = ppw[1] / ppw[0];
#pragma unroll
            for (int mi = 0; mi < 2; mi++)
#pragma unroll
                for (int ni = 0; ni < 8; ni++)
#pragma unroll
                    for (int k = 0; k < 4; k++) acc[mi][ni][k] *= f;
        }
    }

    // ---- epilogue: transpose acc through smem, then coalesced per-channel IO ----
    __syncthreads();                       // mainloop smem reads complete
    float* smt = (float*)smw;              // 128 rows x 132 pitch = 67584 B
#pragma unroll
    for (int mi = 0; mi < 2; mi++)
#pragma unroll
        for (int half = 0; half < 2; half++) {
            int row = wm + mi * 16 + half * 8 + l4;
#pragma unroll
            for (int ni = 0; ni < 8; ni++) {
                int col = wn + ni * 8 + q * 2;
                *(float2*)&smt[row * 132 + col] =
                    make_float2(acc[mi][ni][half * 2 + 0], acc[mi][ni][half * 2 + 1]);
            }
        }
    __syncthreads();

    const int ol = tid >> 1;               // output channel (local)
    const int ch = tid & 1;                // n half (64 n each)
    const int o  = m0 + ol;
    const float* srow = smt + ol * 132 + ch * 64;
    const int hwb = (n0 + ch * 64) >> 2;   // 16 hw per thread

    if (STAGE == 1) {
        int e = pe[0];
        float alpha = bnsg[e * C + o] * rinv;
        float beta  = bg[e * C + o] * alpha + bnbg[e * C + o];
#pragma unroll
        for (int cb = 0; cb < 2; cb++) {
            int hw0 = hwb + cb * 8;
            float vb[32];
#pragma unroll
            for (int i = 0; i < 8; i++) {
                float4 gg = *(const float4*)(srow + cb * 32 + i * 4);
                vb[i * 4 + 0] = gg.x; vb[i * 4 + 1] = gg.y;
                vb[i * 4 + 2] = gg.z; vb[i * 4 + 3] = gg.w;
            }
#pragma unroll
            for (int t = 0; t < T; t++) {
                const float* xs = x + (((size_t)t * BSZ + b) * C + o) * HW + hw0;
                float4 xa = *(const float4*)xs;
                float4 xc = *(const float4*)(xs + 4);
#pragma unroll
                for (int i = 0; i < 4; i++) {
                    float g0 = vb[i * 4 + t] + beta;          // acc + beta (order preserved)
                    vb[i * 4 + t] = ((const float*)&xa)[i] + g0;
                }
#pragma unroll
                for (int i = 0; i < 4; i++) {
                    float g0 = vb[(i + 4) * 4 + t] + beta;
                    vb[(i + 4) * 4 + t] = ((const float*)&xc)[i] + g0;
                }
            }
            float* hd = g_H1 + (((size_t)pbase * C + o) * HW + hw0) * T;
#pragma unroll
            for (int i = 0; i < 8; i++)
                *(float4*)(hd + i * 4) =
                    make_float4(vb[i * 4], vb[i * 4 + 1], vb[i * 4 + 2], vb[i * 4 + 3]);
        }
    } else {
        float pw0 = ppw[0], pw1 = ppw[1];
        float a0 = bnsg[pe[0] * C + o] * rinv;
        float a1 = bnsg[pe[1] * C + o] * rinv;
        float be0 = bg[pe[0] * C + o] * a0 + bnbg[pe[0] * C + o];
        float be1 = bg[pe[1] * C + o] * a1 + bnbg[pe[1] * C + o];
#pragma unroll
        for (int cb = 0; cb < 2; cb++) {
            int hw0 = hwb + cb * 8;
            const float* h0p = g_H1 + (((size_t)(pbase + 0) * C + o) * HW + hw0) * T;
            const float* h1p = g_H1 + (((size_t)(pbase + 1) * C + o) * HW + hw0) * T;
            float vb[32];
#pragma unroll
            for (int i = 0; i < 8; i++) {
                float4 gg = *(const float4*)(srow + cb * 32 + i * 4);
                float4 h0 = *(const float4*)(h0p + i * 4);
                float4 h1 = *(const float4*)(h1p + i * 4);
#pragma unroll
                for (int jj = 0; jj < 4; jj++) {
                    // acc = S0 + (pw1/pw0)*S1 -> out = pw0*(acc + h0 + be0) + pw1*(h1 + be1)
                    vb[i * 4 + jj] = pw0 * (((const float*)&gg)[jj] + ((const float*)&h0)[jj] + be0)
                                   + pw1 * (((const float*)&h1)[jj] + be1);
                }
            }
#pragma unroll
            for (int t = 0; t < T; t++) {
                float* od = outp + (((size_t)t * BSZ + b) * C + o) * HW + hw0;
                *(float4*)od       = make_float4(vb[0 * 4 + t], vb[1 * 4 + t], vb[2 * 4 + t], vb[3 * 4 + t]);
                *(float4*)(od + 4) = make_float4(vb[4 * 4 + t], vb[5 * 4 + t], vb[6 * 4 + t], vb[7 * 4 + t]);
            }
        }
    }
}

// ---------------- launcher ----------------
extern "C" void kernel_launch(void* const* d_in, const int* in_sizes, int n_in,
                              void* d_out, int out_size) {
    const float* x   = (const float*)d_in[0];
    const float* rW  = (const float*)d_in[1];
    const float* rb  = (const float*)d_in[2];
    const float* rbs = (const float*)d_in[3];
    const float* rbb = (const float*)d_in[4];
    const float* W1  = (const float*)d_in[5];
    const float* b1  = (const float*)d_in[6];
    const float* s1  = (const float*)d_in[7];
    const float* bb1 = (const float*)d_in[8];
    const float* W2  = (const float*)d_in[9];
    const float* b2  = (const float*)d_in[10];
    const float* s2  = (const float*)d_in[11];
    const float* bb2 = (const float*)d_in[12];
    float* out = (float*)d_out;

    cudaFuncSetAttribute(expert_kernel<1>, cudaFuncAttributeMaxDynamicSharedMemorySize, SMEM_BYTES);
    cudaFuncSetAttribute(expert_kernel<2>, cudaFuncAttributeMaxDynamicSharedMemorySize, SMEM_BYTES);

    wtrans_kernel<<<288, 256>>>(W1, s1, 0);
    wtrans_kernel<<<288, 256>>>(W2, s2, 8);
    router_s_kernel<<<BSZ * C, 256>>>(x);
    routing_dot<<<128, 128>>>(rW, rb, rbs, rbb);
    routing_top2<<<1, 16>>>();

    spike1_kernel<<<(BSZ * 192 * 128) / 256, 256>>>(x);
    dim3 grid1(NCOL / BN, C / BM, 32);
    expert_kernel<1><<<grid1, NTHREADS, SMEM_BYTES>>>(x, b1, s1, bb1, out);

    spike2_kernel<<<(32 * 192 * 128) / 256, 256>>>();
    dim3 grid2(NCOL / BN, C / BM, 16);
    expert_kernel<2><<<grid2, NTHREADS, SMEM_BYTES>>>(x, b2, s2, bb2, out);
}